// round 3
// baseline (speedup 1.0000x reference)
#include <cuda_runtime.h>
#include <cstdint>

// Problem constants
#define BB 8
#define TT 256
#define UU 64
#define DD 512
#define VV 1024
#define M_TOTAL 131072   // BB*TT*UU

// Tiling
#define BM 128
#define BN 256
#define BK 32            // fp32 elements per K-chunk (=128 bytes/row, SW128 atom)
#define NCHUNK (DD / BK) // 16
#define THREADS 256

// SMEM layout (relative to a 1024-aligned base inside dynamic smem)
#define SM_TMEM   0
#define SM_MBAR0  8
#define SM_MBAR1  16
#define SM_BIAS   1024                 // 256 floats (bias tile)
#define SM_A0     2048                 // 128x32 fp32 = 16384 B
#define SM_A1     (SM_A0 + 16384)      // 18432
#define SM_B0     (SM_A1 + 16384)      // 34816 (1024-aligned)
#define SM_B1     (SM_B0 + 32768)      // 67584
#define SM_END    (SM_B1 + 32768)      // 100352
#define SMEM_DYN  (SM_END + 1024)      // + alignment slack

// tcgen05 only exists on the arch-specific target (sm_103a). The harness's
// nvcc also runs a generic compute_103 PTX pass; give that pass a SIMT
// fallback body so ptxas doesn't abort. At runtime the sm_103a cubin is used.
#if !defined(__CUDA_ARCH__) || defined(__CUDA_ARCH_FEAT_SM103_ALL) || \
    defined(__CUDA_ARCH_SPECIFIC__) || defined(__CUDA_ARCH_FAMILY_SPECIFIC__)
#define HAS_TCGEN05 1
#else
#define HAS_TCGEN05 0
#endif

// SW128 K-major smem descriptor base: layout=SW128(2), version=1(Blackwell), SBO=64, LBO=1
static constexpr unsigned long long DESC_BASE =
    (2ULL << 61) | (1ULL << 46) | (64ULL << 32) | (1ULL << 16);

// idesc for kind::tf32: c=F32(1@[4]), a=TF32(2@[7]), b=TF32(2@[10]), N/8@[17], M/16@[24]
#define IDESC ((1u << 4) | (2u << 7) | (2u << 10) | ((BN / 8) << 17) | ((BM / 16) << 24))

// ---------------- inline PTX helpers ----------------

__device__ __forceinline__ uint32_t cvta_shared_u32(const void* p) {
    uint32_t a;
    asm("{ .reg .u64 t; cvta.to.shared.u64 t, %1; cvt.u32.u64 %0, t; }" : "=r"(a) : "l"(p));
    return a;
}

#if HAS_TCGEN05
__device__ __forceinline__ bool elect_one() {
    uint32_t p;
    asm volatile(
        "{ .reg .pred P; elect.sync _|P, 0xFFFFFFFF; selp.b32 %0, 1, 0, P; }" : "=r"(p));
    return p != 0;
}

__device__ __forceinline__ void mbar_wait(uint32_t addr, uint32_t parity) {
    asm volatile(
        "{\n\t.reg .pred P;\n\t"
        "WL%=:\n\t"
        "mbarrier.try_wait.parity.acquire.cta.shared::cta.b64 P, [%0], %1, 0x989680;\n\t"
        "@P bra.uni WD%=;\n\t"
        "bra.uni WL%=;\n\t"
        "WD%=:\n\t}"
        :: "r"(addr), "r"(parity) : "memory");
}

__device__ __forceinline__ uint32_t relu_tf32(float a, float b) {
    float v = fmaxf(a + b, 0.0f);
    uint32_t r;
    asm("cvt.rna.tf32.f32 %0, %1;" : "=r"(r) : "f"(v));
    return r;
}

__device__ __forceinline__ uint32_t f2tf(float v) {
    uint32_t r;
    asm("cvt.rna.tf32.f32 %0, %1;" : "=r"(r) : "f"(v));
    return r;
}

__device__ __forceinline__ void mma_tf32(uint32_t d_tmem, uint64_t a_desc, uint64_t b_desc,
                                         uint32_t idesc, uint32_t en) {
    asm volatile(
        "{\n\t.reg .pred p;\n\t"
        "setp.ne.u32 p, %5, 0;\n\t"
        "tcgen05.mma.cta_group::1.kind::tf32 [%0], %1, %2, %3, {%4, %4, %4, %4}, p;\n\t}"
        :: "r"(d_tmem), "l"(a_desc), "l"(b_desc), "r"(idesc), "r"(0u), "r"(en)
        : "memory");
}
#endif // HAS_TCGEN05

// ---------------- main kernel ----------------

__global__ void __launch_bounds__(THREADS, 2)
joiner_tf32_kernel(const float* __restrict__ src,   // [B,T,D]
                   const float* __restrict__ tgt,   // [B,U,D]
                   const float* __restrict__ Wm,    // [V,D]
                   const float* __restrict__ bias,  // [V]
                   float* __restrict__ out)         // [M_TOTAL, V]
{
#if HAS_TCGEN05
    extern __shared__ char smem_raw[];
    uint32_t sb = (cvta_shared_u32(smem_raw) + 1023u) & ~1023u;

    const int tid = threadIdx.x;
    const int wid = tid >> 5;
    const int lid = tid & 31;
    const int m0 = blockIdx.y * BM;
    const int n0 = blockIdx.x * BN;

    if (tid == 0) {
        asm volatile("mbarrier.init.shared.b64 [%0], 1;" :: "r"(sb + SM_MBAR0) : "memory");
        asm volatile("mbarrier.init.shared.b64 [%0], 1;" :: "r"(sb + SM_MBAR1) : "memory");
    }
    if (wid == 0) {
        asm volatile("tcgen05.alloc.cta_group::1.sync.aligned.shared::cta.b32 [%0], %1;"
                     :: "r"(sb + SM_TMEM), "r"(256u) : "memory");
        asm volatile("tcgen05.relinquish_alloc_permit.cta_group::1.sync.aligned;");
    }
    {   // bias tile into smem
        float bv = bias[n0 + tid];
        asm volatile("st.shared.f32 [%0], %1;" :: "r"(sb + SM_BIAS + tid * 4), "f"(bv));
    }
    __syncthreads();

    uint32_t tmem;
    asm volatile("ld.shared.b32 %0, [%1];" : "=r"(tmem) : "r"(sb + SM_TMEM));

    const uint64_t dA0 = DESC_BASE | ((uint64_t)((sb + SM_A0) >> 4) & 0x3FFF);
    const uint64_t dA1 = DESC_BASE | ((uint64_t)((sb + SM_A1) >> 4) & 0x3FFF);
    const uint64_t dB0 = DESC_BASE | ((uint64_t)((sb + SM_B0) >> 4) & 0x3FFF);
    const uint64_t dB1 = DESC_BASE | ((uint64_t)((sb + SM_B1) >> 4) & 0x3FFF);

#pragma unroll 1
    for (int i = 0; i < NCHUNK; ++i) {
        const int buf = i & 1;
        // wait until the MMAs that last read this buffer (chunk i-2) completed
        if (i >= 2) mbar_wait(sb + SM_MBAR0 + buf * 8, ((i >> 1) - 1) & 1);

        const int kc0 = i * BK;
        const uint32_t aB = sb + (buf ? SM_A1 : SM_A0);
        const uint32_t bB = sb + (buf ? SM_B1 : SM_B0);

        // ---- A tile: relu(src + tgt) -> tf32, SW128-swizzled STS.128 ----
        // 128 rows x 32 cols = 1024 float4 groups; 4 per thread
#pragma unroll
        for (int s = 0; s < 4; ++s) {
            int g = tid + s * THREADS;
            int r = g >> 3, j4 = g & 7;
            int m = m0 + r;
            int bi = m >> 14;           // / (T*U)
            int ti = (m >> 6) & 255;    // / U % T
            int ui = m & 63;            // % U
            const float4 s4 = *reinterpret_cast<const float4*>(
                src + (size_t)(bi * TT + ti) * DD + kc0 + (j4 << 2));
            const float4 t4 = *reinterpret_cast<const float4*>(
                tgt + (size_t)(bi * UU + ui) * DD + kc0 + (j4 << 2));
            uint32_t x0 = relu_tf32(s4.x, t4.x);
            uint32_t x1 = relu_tf32(s4.y, t4.y);
            uint32_t x2 = relu_tf32(s4.z, t4.z);
            uint32_t x3 = relu_tf32(s4.w, t4.w);
            uint32_t off = (uint32_t)((r << 7) + (j4 << 4));
            off ^= (off >> 3) & 0x70;   // SW128
            asm volatile("st.shared.v4.b32 [%0], {%1, %2, %3, %4};"
                         :: "r"(aB + off), "r"(x0), "r"(x1), "r"(x2), "r"(x3));
        }

        // ---- B tile: W rows [n0, n0+256), K chunk -> tf32, swizzled ----
        // 256 rows x 32 cols = 2048 float4 groups; 8 per thread
#pragma unroll
        for (int s = 0; s < 8; ++s) {
            int g = tid + s * THREADS;
            int r = g >> 3, j4 = g & 7;
            const float4 w4 = *reinterpret_cast<const float4*>(
                Wm + (size_t)(n0 + r) * DD + kc0 + (j4 << 2));
            uint32_t x0 = f2tf(w4.x);
            uint32_t x1 = f2tf(w4.y);
            uint32_t x2 = f2tf(w4.z);
            uint32_t x3 = f2tf(w4.w);
            uint32_t off = (uint32_t)((r << 7) + (j4 << 4));
            off ^= (off >> 3) & 0x70;
            asm volatile("st.shared.v4.b32 [%0], {%1, %2, %3, %4};"
                         :: "r"(bB + off), "r"(x0), "r"(x1), "r"(x2), "r"(x3));
        }

        asm volatile("fence.proxy.async.shared::cta;" ::: "memory");
        __syncthreads();

        // ---- issue 4 MMAs (K=8 each) for this chunk, then commit to this buffer's mbar ----
        if (wid == 0) {
            uint64_t da = buf ? dA1 : dA0;
            uint64_t db = buf ? dB1 : dB0;
            if (elect_one()) {
#pragma unroll
                for (int ks = 0; ks < 4; ++ks) {
                    uint32_t en = (i | ks) ? 1u : 0u;   // first MMA overwrites D
                    mma_tf32(tmem, da + ks * 2, db + ks * 2, IDESC, en);
                }
                asm volatile(
                    "tcgen05.commit.cta_group::1.mbarrier::arrive::one.shared::cluster.b64 [%0];"
                    :: "r"(sb + SM_MBAR0 + buf * 8) : "memory");
            }
        }
    }

    // wait for the 8th (final) commit on each buffer's mbar: parity (8-1)&1 = 1
    mbar_wait(sb + SM_MBAR0, 1);
    mbar_wait(sb + SM_MBAR1, 1);
    asm volatile("tcgen05.fence::after_thread_sync;" ::: "memory");

    // ---- epilogue: TMEM -> +bias -> GMEM ----
    // warps 0-3 handle cols [0,128), warps 4-7 cols [128,256); rows = (wid&3)*32 + lid
    const int rowLane = (wid & 3) * 32 + lid;
    const int colHalf = (wid >> 2) * 128;
    float* orow = out + (size_t)(m0 + rowLane) * VV + n0;

#pragma unroll 1
    for (int itc = 0; itc < 4; ++itc) {
        int cb = colHalf + itc * 32;
        uint32_t d[32];
        asm volatile(
            "tcgen05.ld.sync.aligned.32x32b.x32.b32 "
            "{%0, %1, %2, %3, %4, %5, %6, %7, "
            " %8, %9, %10, %11, %12, %13, %14, %15, "
            " %16, %17, %18, %19, %20, %21, %22, %23, "
            " %24, %25, %26, %27, %28, %29, %30, %31}, [%32];"
            : "=r"(d[0]), "=r"(d[1]), "=r"(d[2]), "=r"(d[3]),
              "=r"(d[4]), "=r"(d[5]), "=r"(d[6]), "=r"(d[7]),
              "=r"(d[8]), "=r"(d[9]), "=r"(d[10]), "=r"(d[11]),
              "=r"(d[12]), "=r"(d[13]), "=r"(d[14]), "=r"(d[15]),
              "=r"(d[16]), "=r"(d[17]), "=r"(d[18]), "=r"(d[19]),
              "=r"(d[20]), "=r"(d[21]), "=r"(d[22]), "=r"(d[23]),
              "=r"(d[24]), "=r"(d[25]), "=r"(d[26]), "=r"(d[27]),
              "=r"(d[28]), "=r"(d[29]), "=r"(d[30]), "=r"(d[31])
            : "r"(tmem + cb));
        asm volatile("tcgen05.wait::ld.sync.aligned;" ::: "memory");

#pragma unroll
        for (int c = 0; c < 32; c += 4) {
            float4 bv;
            asm volatile("ld.shared.v4.f32 {%0, %1, %2, %3}, [%4];"
                         : "=f"(bv.x), "=f"(bv.y), "=f"(bv.z), "=f"(bv.w)
                         : "r"(sb + SM_BIAS + (cb + c) * 4));
            float4 v;
            v.x = __uint_as_float(d[c + 0]) + bv.x;
            v.y = __uint_as_float(d[c + 1]) + bv.y;
            v.z = __uint_as_float(d[c + 2]) + bv.z;
            v.w = __uint_as_float(d[c + 3]) + bv.w;
            *reinterpret_cast<float4*>(orow + cb + c) = v;
        }
    }

    __syncthreads();
    if (wid == 0) {
        asm volatile("tcgen05.dealloc.cta_group::1.sync.aligned.b32 %0, %1;"
                     :: "r"(tmem), "r"(256u));
    }
#else
    // ---- generic-PTX fallback (compute_103 pass only; never runs on sm_103a) ----
    const int tid = threadIdx.x;
    const int m0 = blockIdx.y * BM;
    const int n0 = blockIdx.x * BN;
    for (int r = 0; r < BM; ++r) {
        int m = m0 + r;
        int bi = m >> 14, ti = (m >> 6) & 255, ui = m & 63;
        const float* sp = src + (size_t)(bi * TT + ti) * DD;
        const float* tp = tgt + (size_t)(bi * UU + ui) * DD;
        for (int c = tid; c < BN; c += THREADS) {
            const float* wp = Wm + (size_t)(n0 + c) * DD;
            float acc = bias[n0 + c];
            for (int k = 0; k < DD; ++k)
                acc += fmaxf(sp[k] + tp[k], 0.0f) * wp[k];
            out[(size_t)m * VV + n0 + c] = acc;
        }
    }
#endif
}

// The harness flattens all reference outputs into one float32 buffer:
// [out (M*V floats), source_lengths (8), target_lengths (8)]. The int32
// lengths are compared after cast to float, so write them as float VALUES.
__global__ void tail_copy_kernel(const int* __restrict__ sl, const int* __restrict__ tl,
                                 float* __restrict__ dst, int extra) {
    int i = threadIdx.x;
    if (i < 8 && extra >= 8)        dst[i] = (float)sl[i];
    else if (i >= 8 && i < 16 && extra >= 16) dst[i] = (float)tl[i - 8];
}

extern "C" void kernel_launch(void* const* d_in, const int* in_sizes, int n_in,
                              void* d_out, int out_size) {
    const float* src  = (const float*)d_in[0];
    const int*   slen = (const int*)d_in[1];
    const float* tgt  = (const float*)d_in[2];
    const int*   tlen = (const int*)d_in[3];
    const float* Wm   = (const float*)d_in[4];
    const float* bias = (const float*)d_in[5];
    float* out = (float*)d_out;

    cudaFuncSetAttribute(joiner_tf32_kernel,
                         cudaFuncAttributeMaxDynamicSharedMemorySize, SMEM_DYN);

    dim3 grid(VV / BN, M_TOTAL / BM);  // (4, 1024)
    joiner_tf32_kernel<<<grid, THREADS, SMEM_DYN>>>(src, tgt, Wm, bias, out);

    long long extra = (long long)out_size - (long long)M_TOTAL * VV;
    if (extra > 0) {
        tail_copy_kernel<<<1, 32>>>(slen, tlen,
                                    (float*)d_out + (long long)M_TOTAL * VV,
                                    (int)(extra > 16 ? 16 : extra));
    }
}

// round 4
// speedup vs baseline: 1.1146x; 1.1146x over previous
#include <cuda_runtime.h>
#include <cstdint>

// Problem constants
#define BB 8
#define TT 256
#define UU 64
#define DD 512
#define VV 1024
#define M_TOTAL 131072   // BB*TT*UU

// Tiling
#define BM 128
#define BN 512           // full half of V per CTA; 2 MMAs of N=256 per K-step
#define BK 32            // fp32 elements per K-chunk (=128 bytes/row, SW128 atom)
#define NCHUNK (DD / BK) // 16
#define THREADS 256

// SMEM layout (relative to a 1024-aligned base inside dynamic smem)
#define SM_TMEM   0
#define SM_MBAR0  8
#define SM_MBAR1  16
#define SM_BIAS   1024                 // 512 floats
#define SM_A0     4096                 // 128x32 fp32 = 16384 B
#define SM_A1     (SM_A0 + 16384)      // 20480
#define SM_B0     (SM_A1 + 16384)      // 36864 (1024-aligned), 512x32 fp32 = 65536 B
#define SM_B1     (SM_B0 + 65536)      // 102400
#define SM_END    (SM_B1 + 65536)      // 167936
#define SMEM_DYN  (SM_END + 1024)

// tcgen05 only exists on the arch-specific target (sm_103a). The harness's
// nvcc also runs a generic compute_103 PTX pass; give that pass a SIMT
// fallback body so ptxas doesn't abort. At runtime the sm_103a cubin is used.
#if !defined(__CUDA_ARCH__) || defined(__CUDA_ARCH_FEAT_SM103_ALL) || \
    defined(__CUDA_ARCH_SPECIFIC__) || defined(__CUDA_ARCH_FAMILY_SPECIFIC__)
#define HAS_TCGEN05 1
#else
#define HAS_TCGEN05 0
#endif

// SW128 K-major smem descriptor base: layout=SW128(2), version=1(Blackwell), SBO=64, LBO=1
static constexpr unsigned long long DESC_BASE =
    (2ULL << 61) | (1ULL << 46) | (64ULL << 32) | (1ULL << 16);

// idesc for kind::tf32: c=F32(1@[4]), a=TF32(2@[7]), b=TF32(2@[10]), N=256(32@[17]), M=128(8@[24])
#define IDESC ((1u << 4) | (2u << 7) | (2u << 10) | (32u << 17) | (8u << 24))

// W pre-converted to tf32 (RNA) once per call
__device__ float g_wtf[VV * DD];

// ---------------- inline PTX helpers ----------------

__device__ __forceinline__ uint32_t cvta_shared_u32(const void* p) {
    uint32_t a;
    asm("{ .reg .u64 t; cvta.to.shared.u64 t, %1; cvt.u32.u64 %0, t; }" : "=r"(a) : "l"(p));
    return a;
}

__device__ __forceinline__ uint32_t f2tf(float v) {
    uint32_t r;
    asm("cvt.rna.tf32.f32 %0, %1;" : "=r"(r) : "f"(v));
    return r;
}

#if HAS_TCGEN05
__device__ __forceinline__ bool elect_one() {
    uint32_t p;
    asm volatile(
        "{ .reg .pred P; elect.sync _|P, 0xFFFFFFFF; selp.b32 %0, 1, 0, P; }" : "=r"(p));
    return p != 0;
}

__device__ __forceinline__ void mbar_wait(uint32_t addr, uint32_t parity) {
    asm volatile(
        "{\n\t.reg .pred P;\n\t"
        "WL%=:\n\t"
        "mbarrier.try_wait.parity.acquire.cta.shared::cta.b64 P, [%0], %1, 0x989680;\n\t"
        "@P bra.uni WD%=;\n\t"
        "bra.uni WL%=;\n\t"
        "WD%=:\n\t}"
        :: "r"(addr), "r"(parity) : "memory");
}

__device__ __forceinline__ uint32_t relu_tf32(float a, float b) {
    float v = fmaxf(a + b, 0.0f);
    uint32_t r;
    asm("cvt.rna.tf32.f32 %0, %1;" : "=r"(r) : "f"(v));
    return r;
}

__device__ __forceinline__ void mma_tf32(uint32_t d_tmem, uint64_t a_desc, uint64_t b_desc,
                                         uint32_t idesc, uint32_t en) {
    asm volatile(
        "{\n\t.reg .pred p;\n\t"
        "setp.ne.u32 p, %5, 0;\n\t"
        "tcgen05.mma.cta_group::1.kind::tf32 [%0], %1, %2, %3, {%4, %4, %4, %4}, p;\n\t}"
        :: "r"(d_tmem), "l"(a_desc), "l"(b_desc), "r"(idesc), "r"(0u), "r"(en)
        : "memory");
}

__device__ __forceinline__ void cp_async16(uint32_t dst, const void* src) {
    asm volatile("cp.async.ca.shared.global [%0], [%1], 16;"
                 :: "r"(dst), "l"(src) : "memory");
}
#endif // HAS_TCGEN05

// ---------------- main kernel ----------------

__global__ void __launch_bounds__(THREADS, 1)
joiner_tf32_kernel(const float* __restrict__ src,   // [B,T,D]
                   const float* __restrict__ tgt,   // [B,U,D]
                   const float* __restrict__ bias,  // [V]
                   float* __restrict__ out)         // [M_TOTAL, V]
{
#if HAS_TCGEN05
    extern __shared__ char smem_raw[];
    uint32_t sb = (cvta_shared_u32(smem_raw) + 1023u) & ~1023u;

    const int tid = threadIdx.x;
    const int wid = tid >> 5;
    const int lid = tid & 31;
    const int m0 = blockIdx.y * BM;
    const int n0 = blockIdx.x * BN;

    if (tid == 0) {
        asm volatile("mbarrier.init.shared.b64 [%0], 1;" :: "r"(sb + SM_MBAR0) : "memory");
        asm volatile("mbarrier.init.shared.b64 [%0], 1;" :: "r"(sb + SM_MBAR1) : "memory");
    }
    if (wid == 0) {
        asm volatile("tcgen05.alloc.cta_group::1.sync.aligned.shared::cta.b32 [%0], %1;"
                     :: "r"(sb + SM_TMEM), "r"(512u) : "memory");
        asm volatile("tcgen05.relinquish_alloc_permit.cta_group::1.sync.aligned;");
    }
    {   // bias tile: 512 floats
        float b0 = bias[n0 + tid];
        float b1 = bias[n0 + 256 + tid];
        asm volatile("st.shared.f32 [%0], %1;" :: "r"(sb + SM_BIAS + tid * 4), "f"(b0));
        asm volatile("st.shared.f32 [%0], %1;" :: "r"(sb + SM_BIAS + (256 + tid) * 4), "f"(b1));
    }
    __syncthreads();

    uint32_t tmem;
    asm volatile("ld.shared.b32 %0, [%1];" : "=r"(tmem) : "r"(sb + SM_TMEM));

    const uint64_t dA0 = DESC_BASE | ((uint64_t)((sb + SM_A0) >> 4) & 0x3FFF);
    const uint64_t dA1 = DESC_BASE | ((uint64_t)((sb + SM_A1) >> 4) & 0x3FFF);
    const uint64_t dB0 = DESC_BASE | ((uint64_t)((sb + SM_B0) >> 4) & 0x3FFF);
    const uint64_t dB1 = DESC_BASE | ((uint64_t)((sb + SM_B1) >> 4) & 0x3FFF);

#pragma unroll 1
    for (int i = 0; i < NCHUNK; ++i) {
        const int buf = i & 1;
        // wait until the MMAs that last read this buffer (chunk i-2) completed
        if (i >= 2) mbar_wait(sb + SM_MBAR0 + buf * 8, ((i >> 1) - 1) & 1);

        const int kc0 = i * BK;
        const uint32_t aB = sb + (buf ? SM_A1 : SM_A0);
        const uint32_t bB = sb + (buf ? SM_B1 : SM_B0);

        // ---- B tile via cp.async: W_tf32 rows [n0, n0+512), this K chunk ----
        // 512 rows x 8 float4 = 4096 ops; 16 per thread
#pragma unroll
        for (int s = 0; s < 16; ++s) {
            int g = tid + s * THREADS;
            int r = g >> 3, j4 = g & 7;
            uint32_t off = (uint32_t)((r << 7) + (j4 << 4));
            off ^= (off >> 3) & 0x70;   // SW128
            cp_async16(bB + off, g_wtf + (size_t)(n0 + r) * DD + kc0 + (j4 << 2));
        }
        asm volatile("cp.async.commit_group;" ::: "memory");

        // ---- A tile: relu(src + tgt) -> tf32, SW128-swizzled STS.128 ----
#pragma unroll
        for (int s = 0; s < 4; ++s) {
            int g = tid + s * THREADS;
            int r = g >> 3, j4 = g & 7;
            int m = m0 + r;
            int bi = m >> 14;           // / (T*U)
            int ti = (m >> 6) & 255;    // / U % T
            int ui = m & 63;            // % U
            const float4 s4 = *reinterpret_cast<const float4*>(
                src + (size_t)(bi * TT + ti) * DD + kc0 + (j4 << 2));
            const float4 t4 = *reinterpret_cast<const float4*>(
                tgt + (size_t)(bi * UU + ui) * DD + kc0 + (j4 << 2));
            uint32_t x0 = relu_tf32(s4.x, t4.x);
            uint32_t x1 = relu_tf32(s4.y, t4.y);
            uint32_t x2 = relu_tf32(s4.z, t4.z);
            uint32_t x3 = relu_tf32(s4.w, t4.w);
            uint32_t off = (uint32_t)((r << 7) + (j4 << 4));
            off ^= (off >> 3) & 0x70;   // SW128
            asm volatile("st.shared.v4.b32 [%0], {%1, %2, %3, %4};"
                         :: "r"(aB + off), "r"(x0), "r"(x1), "r"(x2), "r"(x3));
        }

        asm volatile("cp.async.wait_group 0;" ::: "memory");
        asm volatile("fence.proxy.async.shared::cta;" ::: "memory");
        __syncthreads();

        // ---- 8 MMAs: 2 N-halves x 4 K-steps, then commit this buffer's mbar ----
        if (wid == 0) {
            uint64_t da = buf ? dA1 : dA0;
            uint64_t db = buf ? dB1 : dB0;
            if (elect_one()) {
#pragma unroll
                for (int h = 0; h < 2; ++h) {
#pragma unroll
                    for (int ks = 0; ks < 4; ++ks) {
                        uint32_t en = (i | ks) ? 1u : 0u;   // first MMA per half overwrites D
                        mma_tf32(tmem + h * 256, da + ks * 2,
                                 db + h * 2048 + ks * 2, IDESC, en);
                    }
                }
                asm volatile(
                    "tcgen05.commit.cta_group::1.mbarrier::arrive::one.shared::cluster.b64 [%0];"
                    :: "r"(sb + SM_MBAR0 + buf * 8) : "memory");
            }
        }
    }

    // final commits: each buffer committed 8 times -> wait parity 1
    mbar_wait(sb + SM_MBAR0, 1);
    mbar_wait(sb + SM_MBAR1, 1);
    asm volatile("tcgen05.fence::after_thread_sync;" ::: "memory");

    // ---- epilogue: TMEM -> +bias -> GMEM ----
    // warps 0-3 cols [0,256), warps 4-7 cols [256,512); rows = (wid&3)*32 + lid
    const int rowLane = (wid & 3) * 32 + lid;
    const int colHalf = (wid >> 2) * 256;
    float* orow = out + (size_t)(m0 + rowLane) * VV + n0;

#pragma unroll 1
    for (int itc = 0; itc < 8; ++itc) {
        int cb = colHalf + itc * 32;
        uint32_t d[32];
        asm volatile(
            "tcgen05.ld.sync.aligned.32x32b.x32.b32 "
            "{%0, %1, %2, %3, %4, %5, %6, %7, "
            " %8, %9, %10, %11, %12, %13, %14, %15, "
            " %16, %17, %18, %19, %20, %21, %22, %23, "
            " %24, %25, %26, %27, %28, %29, %30, %31}, [%32];"
            : "=r"(d[0]), "=r"(d[1]), "=r"(d[2]), "=r"(d[3]),
              "=r"(d[4]), "=r"(d[5]), "=r"(d[6]), "=r"(d[7]),
              "=r"(d[8]), "=r"(d[9]), "=r"(d[10]), "=r"(d[11]),
              "=r"(d[12]), "=r"(d[13]), "=r"(d[14]), "=r"(d[15]),
              "=r"(d[16]), "=r"(d[17]), "=r"(d[18]), "=r"(d[19]),
              "=r"(d[20]), "=r"(d[21]), "=r"(d[22]), "=r"(d[23]),
              "=r"(d[24]), "=r"(d[25]), "=r"(d[26]), "=r"(d[27]),
              "=r"(d[28]), "=r"(d[29]), "=r"(d[30]), "=r"(d[31])
            : "r"(tmem + cb));
        asm volatile("tcgen05.wait::ld.sync.aligned;" ::: "memory");

#pragma unroll
        for (int c = 0; c < 32; c += 4) {
            float4 bv;
            asm volatile("ld.shared.v4.f32 {%0, %1, %2, %3}, [%4];"
                         : "=f"(bv.x), "=f"(bv.y), "=f"(bv.z), "=f"(bv.w)
                         : "r"(sb + SM_BIAS + (cb + c) * 4));
            float4 v;
            v.x = __uint_as_float(d[c + 0]) + bv.x;
            v.y = __uint_as_float(d[c + 1]) + bv.y;
            v.z = __uint_as_float(d[c + 2]) + bv.z;
            v.w = __uint_as_float(d[c + 3]) + bv.w;
            *reinterpret_cast<float4*>(orow + cb + c) = v;
        }
    }

    __syncthreads();
    if (wid == 0) {
        asm volatile("tcgen05.dealloc.cta_group::1.sync.aligned.b32 %0, %1;"
                     :: "r"(tmem), "r"(512u));
    }
#else
    // ---- generic-PTX fallback (compute_103 pass only; never runs on sm_103a) ----
    const int tid = threadIdx.x;
    const int m0 = blockIdx.y * BM;
    const int n0 = blockIdx.x * BN;
    for (int r = 0; r < BM; ++r) {
        int m = m0 + r;
        int bi = m >> 14, ti = (m >> 6) & 255, ui = m & 63;
        const float* sp = src + (size_t)(bi * TT + ti) * DD;
        const float* tp = tgt + (size_t)(bi * UU + ui) * DD;
        for (int c = tid; c < BN; c += THREADS) {
            const float* wp = g_wtf + (size_t)(n0 + c) * DD;
            float acc = bias[n0 + c];
            for (int k = 0; k < DD; ++k)
                acc += fmaxf(sp[k] + tp[k], 0.0f) * wp[k];
            out[(size_t)m * VV + n0 + c] = acc;
        }
    }
#endif
}

// Prep kernel: convert W -> tf32 (RNA) into g_wtf, and write the two length
// arrays (cast to float values — the harness compares the flat buffer as f32).
__global__ void prep_kernel(const float* __restrict__ Wm,
                            const int* __restrict__ sl, const int* __restrict__ tl,
                            float* __restrict__ tail_dst, int extra) {
    int idx = blockIdx.x * 256 + threadIdx.x;     // 131072 float4 groups
    const float4 w4 = *reinterpret_cast<const float4*>(Wm + (size_t)idx * 4);
    float4 o;
    o.x = __uint_as_float(f2tf(w4.x));
    o.y = __uint_as_float(f2tf(w4.y));
    o.z = __uint_as_float(f2tf(w4.z));
    o.w = __uint_as_float(f2tf(w4.w));
    *reinterpret_cast<float4*>(g_wtf + (size_t)idx * 4) = o;

    if (blockIdx.x == 0) {
        int i = threadIdx.x;
        if (i < 8 && extra >= 8)                        tail_dst[i] = (float)sl[i];
        else if (i >= 8 && i < 16 && extra >= 16)       tail_dst[i] = (float)tl[i - 8];
    }
}

extern "C" void kernel_launch(void* const* d_in, const int* in_sizes, int n_in,
                              void* d_out, int out_size) {
    const float* src  = (const float*)d_in[0];
    const int*   slen = (const int*)d_in[1];
    const float* tgt  = (const float*)d_in[2];
    const int*   tlen = (const int*)d_in[3];
    const float* Wm   = (const float*)d_in[4];
    const float* bias = (const float*)d_in[5];
    float* out = (float*)d_out;

    long long extra = (long long)out_size - (long long)M_TOTAL * VV;
    int extra_c = (int)(extra < 0 ? 0 : (extra > 16 ? 16 : extra));
    prep_kernel<<<VV * DD / 1024, 256>>>(Wm, slen, tlen,
                                         (float*)d_out + (long long)M_TOTAL * VV, extra_c);

    cudaFuncSetAttribute(joiner_tf32_kernel,
                         cudaFuncAttributeMaxDynamicSharedMemorySize, SMEM_DYN);
    dim3 grid(VV / BN, M_TOTAL / BM);  // (2, 1024)
    joiner_tf32_kernel<<<grid, THREADS, SMEM_DYN>>>(src, tgt, bias, out);
}

// round 6
// speedup vs baseline: 1.2166x; 1.0915x over previous
#include <cuda_runtime.h>
#include <cstdint>

// Problem constants
#define BB 8
#define TT 256
#define UU 64
#define DD 512
#define VV 1024
#define M_TOTAL 131072   // BB*TT*UU

// Tiling
#define BM 128
#define BN 256
#define BK 32            // fp32 elements per K-chunk (=128 bytes/row, SW128 atom)
#define NCHUNK (DD / BK) // 16
#define THREADS 256

// SMEM layout (relative to a 1024-aligned base inside dynamic smem)
#define SM_TMEM   0
#define SM_MBAR0  8
#define SM_MBAR1  16
#define SM_BIAS   1024                 // 256 floats
#define SM_A0     2048                 // 128x32 fp32 = 16384 B
#define SM_A1     (SM_A0 + 16384)      // 18432
#define SM_B0     (SM_A1 + 16384)      // 34816 (1024-aligned), 256x32 fp32 = 32768 B
#define SM_B1     (SM_B0 + 32768)      // 67584
#define SM_END    (SM_B1 + 32768)      // 100352
#define SMEM_DYN  (SM_END + 1024)      // ~99 KB -> 2 CTAs/SM

// tcgen05 only exists on the arch-specific target (sm_103a). The harness's
// nvcc also runs a generic compute_103 PTX pass; give that pass a SIMT
// fallback body so ptxas doesn't abort. At runtime the sm_103a cubin is used.
#if !defined(__CUDA_ARCH__) || defined(__CUDA_ARCH_FEAT_SM103_ALL) || \
    defined(__CUDA_ARCH_SPECIFIC__) || defined(__CUDA_ARCH_FAMILY_SPECIFIC__)
#define HAS_TCGEN05 1
#else
#define HAS_TCGEN05 0
#endif

// SW128 K-major smem descriptor base: layout=SW128(2), version=1(Blackwell), SBO=64, LBO=1
static constexpr unsigned long long DESC_BASE =
    (2ULL << 61) | (1ULL << 46) | (64ULL << 32) | (1ULL << 16);

// idesc for kind::tf32: c=F32(1@[4]), a=TF32(2@[7]), b=TF32(2@[10]), N=256(32@[17]), M=128(8@[24])
#define IDESC ((1u << 4) | (2u << 7) | (2u << 10) | (32u << 17) | (8u << 24))

// W pre-converted to tf32 (RNA) once per call
__device__ float g_wtf[VV * DD];

// ---------------- inline PTX helpers ----------------

__device__ __forceinline__ uint32_t cvta_shared_u32(const void* p) {
    uint32_t a;
    asm("{ .reg .u64 t; cvta.to.shared.u64 t, %1; cvt.u32.u64 %0, t; }" : "=r"(a) : "l"(p));
    return a;
}

__device__ __forceinline__ uint32_t f2tf(float v) {
    uint32_t r;
    asm("cvt.rna.tf32.f32 %0, %1;" : "=r"(r) : "f"(v));
    return r;
}

#if HAS_TCGEN05
__device__ __forceinline__ bool elect_one() {
    uint32_t p;
    asm volatile(
        "{ .reg .pred P; elect.sync _|P, 0xFFFFFFFF; selp.b32 %0, 1, 0, P; }" : "=r"(p));
    return p != 0;
}

__device__ __forceinline__ void mbar_wait(uint32_t addr, uint32_t parity) {
    asm volatile(
        "{\n\t.reg .pred P;\n\t"
        "WL%=:\n\t"
        "mbarrier.try_wait.parity.acquire.cta.shared::cta.b64 P, [%0], %1, 0x989680;\n\t"
        "@P bra.uni WD%=;\n\t"
        "bra.uni WL%=;\n\t"
        "WD%=:\n\t}"
        :: "r"(addr), "r"(parity) : "memory");
}

__device__ __forceinline__ uint32_t relu_tf32(float a, float b) {
    float v = fmaxf(a + b, 0.0f);
    uint32_t r;
    asm("cvt.rna.tf32.f32 %0, %1;" : "=r"(r) : "f"(v));
    return r;
}

__device__ __forceinline__ void mma_tf32(uint32_t d_tmem, uint64_t a_desc, uint64_t b_desc,
                                         uint32_t idesc, uint32_t en) {
    asm volatile(
        "{\n\t.reg .pred p;\n\t"
        "setp.ne.u32 p, %5, 0;\n\t"
        "tcgen05.mma.cta_group::1.kind::tf32 [%0], %1, %2, %3, {%4, %4, %4, %4}, p;\n\t}"
        :: "r"(d_tmem), "l"(a_desc), "l"(b_desc), "r"(idesc), "r"(0u), "r"(en)
        : "memory");
}

__device__ __forceinline__ void cp_async16(uint32_t dst, const void* src) {
    asm volatile("cp.async.cg.shared.global [%0], [%1], 16;"
                 :: "r"(dst), "l"(src) : "memory");
}
#endif // HAS_TCGEN05

// ---------------- main kernel ----------------

__global__ void __launch_bounds__(THREADS, 2)
joiner_tf32_kernel(const float* __restrict__ src,   // [B,T,D]
                   const float* __restrict__ tgt,   // [B,U,D]
                   const float* __restrict__ bias,  // [V]
                   float* __restrict__ out)         // [M_TOTAL, V]
{
#if HAS_TCGEN05
    extern __shared__ char smem_raw[];
    uint32_t sb = (cvta_shared_u32(smem_raw) + 1023u) & ~1023u;

    const int tid = threadIdx.x;
    const int wid = tid >> 5;
    const int lid = tid & 31;
    const int m0 = blockIdx.y * BM;
    const int n0 = blockIdx.x * BN;

    if (tid == 0) {
        asm volatile("mbarrier.init.shared.b64 [%0], 1;" :: "r"(sb + SM_MBAR0) : "memory");
        asm volatile("mbarrier.init.shared.b64 [%0], 1;" :: "r"(sb + SM_MBAR1) : "memory");
    }
    if (wid == 0) {
        asm volatile("tcgen05.alloc.cta_group::1.sync.aligned.shared::cta.b32 [%0], %1;"
                     :: "r"(sb + SM_TMEM), "r"(256u) : "memory");
        asm volatile("tcgen05.relinquish_alloc_permit.cta_group::1.sync.aligned;");
    }
    {   // bias tile: 256 floats
        float b0 = bias[n0 + tid];
        asm volatile("st.shared.f32 [%0], %1;" :: "r"(sb + SM_BIAS + tid * 4), "f"(b0));
    }

    // ---- hoisted per-thread addressing ----
    const int r0 = tid >> 3;          // 0..31
    const int j4 = tid & 7;           // float4 column group
    uint32_t swBase = (uint32_t)((r0 << 7) + (j4 << 4));
    swBase ^= (swBase >> 3) & 0x70;   // SW128 (invariant under +32-row steps)

    // A: rows r0+32s (s=0..3); decode (b,t,u) once, advance 128 B per chunk
    const float* sp[4];
    const float* tp[4];
#pragma unroll
    for (int s = 0; s < 4; ++s) {
        int m = m0 + r0 + 32 * s;
        int bi = m >> 14, ti = (m >> 6) & 255, ui = m & 63;
        sp[s] = src + (size_t)(bi * TT + ti) * DD + (j4 << 2);
        tp[s] = tgt + (size_t)(bi * UU + ui) * DD + (j4 << 2);
    }
    // B: rows n0+r0+32s (s=0..7); one base pointer, constant s-offsets
    const float* bp = g_wtf + (size_t)(n0 + r0) * DD + (j4 << 2);

    __syncthreads();

    uint32_t tmem;
    asm volatile("ld.shared.b32 %0, [%1];" : "=r"(tmem) : "r"(sb + SM_TMEM));

    const uint64_t dA0 = DESC_BASE | ((uint64_t)((sb + SM_A0) >> 4) & 0x3FFF);
    const uint64_t dA1 = DESC_BASE | ((uint64_t)((sb + SM_A1) >> 4) & 0x3FFF);
    const uint64_t dB0 = DESC_BASE | ((uint64_t)((sb + SM_B0) >> 4) & 0x3FFF);
    const uint64_t dB1 = DESC_BASE | ((uint64_t)((sb + SM_B1) >> 4) & 0x3FFF);

#pragma unroll 1
    for (int i = 0; i < NCHUNK; ++i) {
        const int buf = i & 1;
        // wait until the MMAs that last read this buffer (chunk i-2) completed
        if (i >= 2) mbar_wait(sb + SM_MBAR0 + buf * 8, ((i >> 1) - 1) & 1);

        const uint32_t aB = sb + (buf ? SM_A1 : SM_A0);
        const uint32_t bB = sb + (buf ? SM_B1 : SM_B0);

        // ---- B tile via cp.async.cg: 256 rows x 32 cols, 8 ops/thread ----
#pragma unroll
        for (int s = 0; s < 8; ++s) {
            cp_async16(bB + swBase + s * 4096u, bp + (size_t)s * 32 * DD);
        }
        asm volatile("cp.async.commit_group;" ::: "memory");

        // ---- A tile: relu(src + tgt) -> tf32, swizzled STS.128 ----
#pragma unroll
        for (int s = 0; s < 4; ++s) {
            const float4 s4 = *reinterpret_cast<const float4*>(sp[s]);
            const float4 t4 = *reinterpret_cast<const float4*>(tp[s]);
            uint32_t x0 = relu_tf32(s4.x, t4.x);
            uint32_t x1 = relu_tf32(s4.y, t4.y);
            uint32_t x2 = relu_tf32(s4.z, t4.z);
            uint32_t x3 = relu_tf32(s4.w, t4.w);
            asm volatile("st.shared.v4.b32 [%0], {%1, %2, %3, %4};"
                         :: "r"(aB + swBase + s * 4096u), "r"(x0), "r"(x1), "r"(x2), "r"(x3));
            sp[s] += BK;
            tp[s] += BK;
        }
        bp += BK;

        asm volatile("cp.async.wait_group 0;" ::: "memory");
        asm volatile("fence.proxy.async.shared::cta;" ::: "memory");
        __syncthreads();

        // ---- 4 MMAs (K=8 each), then commit this buffer's mbar ----
        if (wid == 0) {
            uint64_t da = buf ? dA1 : dA0;
            uint64_t db = buf ? dB1 : dB0;
            if (elect_one()) {
#pragma unroll
                for (int ks = 0; ks < 4; ++ks) {
                    uint32_t en = (i | ks) ? 1u : 0u;   // first MMA overwrites D
                    mma_tf32(tmem, da + ks * 2, db + ks * 2, IDESC, en);
                }
                asm volatile(
                    "tcgen05.commit.cta_group::1.mbarrier::arrive::one.shared::cluster.b64 [%0];"
                    :: "r"(sb + SM_MBAR0 + buf * 8) : "memory");
            }
        }
    }

    // final commits: each buffer committed 8 times -> wait parity 1
    mbar_wait(sb + SM_MBAR0, 1);
    mbar_wait(sb + SM_MBAR1, 1);
    asm volatile("tcgen05.fence::after_thread_sync;" ::: "memory");

    // ---- epilogue: TMEM -> +bias -> GMEM ----
    // warps 0-3 cols [0,128), warps 4-7 cols [128,256); rows = (wid&3)*32 + lid
    const int rowLane = (wid & 3) * 32 + lid;
    const int colHalf = (wid >> 2) * 128;
    float* orow = out + (size_t)(m0 + rowLane) * VV + n0;

#pragma unroll 1
    for (int itc = 0; itc < 4; ++itc) {
        int cb = colHalf + itc * 32;
        uint32_t d[32];
        asm volatile(
            "tcgen05.ld.sync.aligned.32x32b.x32.b32 "
            "{%0, %1, %2, %3, %4, %5, %6, %7, "
            " %8, %9, %10, %11, %12, %13, %14, %15, "
            " %16, %17, %18, %19, %20, %21, %22, %23, "
            " %24, %25, %26, %27, %28, %29, %30, %31}, [%32];"
            : "=r"(d[0]), "=r"(d[1]), "=r"(d[2]), "=r"(d[3]),
              "=r"(d[4]), "=r"(d[5]), "=r"(d[6]), "=r"(d[7]),
              "=r"(d[8]), "=r"(d[9]), "=r"(d[10]), "=r"(d[11]),
              "=r"(d[12]), "=r"(d[13]), "=r"(d[14]), "=r"(d[15]),
              "=r"(d[16]), "=r"(d[17]), "=r"(d[18]), "=r"(d[19]),
              "=r"(d[20]), "=r"(d[21]), "=r"(d[22]), "=r"(d[23]),
              "=r"(d[24]), "=r"(d[25]), "=r"(d[26]), "=r"(d[27]),
              "=r"(d[28]), "=r"(d[29]), "=r"(d[30]), "=r"(d[31])
            : "r"(tmem + cb));
        asm volatile("tcgen05.wait::ld.sync.aligned;" ::: "memory");

#pragma unroll
        for (int c = 0; c < 32; c += 4) {
            float4 bv;
            asm volatile("ld.shared.v4.f32 {%0, %1, %2, %3}, [%4];"
                         : "=f"(bv.x), "=f"(bv.y), "=f"(bv.z), "=f"(bv.w)
                         : "r"(sb + SM_BIAS + (cb + c) * 4));
            float4 v;
            v.x = __uint_as_float(d[c + 0]) + bv.x;
            v.y = __uint_as_float(d[c + 1]) + bv.y;
            v.z = __uint_as_float(d[c + 2]) + bv.z;
            v.w = __uint_as_float(d[c + 3]) + bv.w;
            *reinterpret_cast<float4*>(orow + cb + c) = v;
        }
    }

    __syncthreads();
    if (wid == 0) {
        asm volatile("tcgen05.dealloc.cta_group::1.sync.aligned.b32 %0, %1;"
                     :: "r"(tmem), "r"(256u));
    }
#else
    // ---- generic-PTX fallback (compute_103 pass only; never runs on sm_103a) ----
    const int tid = threadIdx.x;
    const int m0 = blockIdx.y * BM;
    const int n0 = blockIdx.x * BN;
    for (int r = 0; r < BM; ++r) {
        int m = m0 + r;
        int bi = m >> 14, ti = (m >> 6) & 255, ui = m & 63;
        const float* spp = src + (size_t)(bi * TT + ti) * DD;
        const float* tpp = tgt + (size_t)(bi * UU + ui) * DD;
        for (int c = tid; c < BN; c += THREADS) {
            const float* wp = g_wtf + (size_t)(n0 + c) * DD;
            float acc = bias[n0 + c];
            for (int k = 0; k < DD; ++k)
                acc += fmaxf(spp[k] + tpp[k], 0.0f) * wp[k];
            out[(size_t)m * VV + n0 + c] = acc;
        }
    }
#endif
}

// Prep kernel: convert W -> tf32 (RNA) into g_wtf, and write the two length
// arrays (cast to float values — the harness compares the flat buffer as f32).
__global__ void prep_kernel(const float* __restrict__ Wm,
                            const int* __restrict__ sl, const int* __restrict__ tl,
                            float* __restrict__ tail_dst, int extra) {
    int idx = blockIdx.x * 256 + threadIdx.x;     // 131072 float4 groups
    const float4 w4 = *reinterpret_cast<const float4*>(Wm + (size_t)idx * 4);
    float4 o;
    o.x = __uint_as_float(f2tf(w4.x));
    o.y = __uint_as_float(f2tf(w4.y));
    o.z = __uint_as_float(f2tf(w4.z));
    o.w = __uint_as_float(f2tf(w4.w));
    *reinterpret_cast<float4*>(g_wtf + (size_t)idx * 4) = o;

    if (blockIdx.x == 0) {
        int i = threadIdx.x;
        if (i < 8 && extra >= 8)                        tail_dst[i] = (float)sl[i];
        else if (i >= 8 && i < 16 && extra >= 16)       tail_dst[i] = (float)tl[i - 8];
    }
}

extern "C" void kernel_launch(void* const* d_in, const int* in_sizes, int n_in,
                              void* d_out, int out_size) {
    const float* src  = (const float*)d_in[0];
    const int*   slen = (const int*)d_in[1];
    const float* tgt  = (const float*)d_in[2];
    const int*   tlen = (const int*)d_in[3];
    const float* Wm   = (const float*)d_in[4];
    const float* bias = (const float*)d_in[5];
    float* out = (float*)d_out;

    long long extra = (long long)out_size - (long long)M_TOTAL * VV;
    int extra_c = (int)(extra < 0 ? 0 : (extra > 16 ? 16 : extra));
    prep_kernel<<<VV * DD / 1024, 256>>>(Wm, slen, tlen,
                                         (float*)d_out + (long long)M_TOTAL * VV, extra_c);

    cudaFuncSetAttribute(joiner_tf32_kernel,
                         cudaFuncAttributeMaxDynamicSharedMemorySize, SMEM_DYN);
    dim3 grid(VV / BN, M_TOTAL / BM);  // (4, 1024)
    joiner_tf32_kernel<<<grid, THREADS, SMEM_DYN>>>(src, tgt, bias, out);
}

// round 9
// speedup vs baseline: 1.3184x; 1.0836x over previous
#include <cuda_runtime.h>
#include <cuda_fp16.h>
#include <cstdint>

// Problem constants
#define BB 8
#define TT 256
#define UU 64
#define DD 512
#define VV 1024
#define M_TOTAL 131072   // BB*TT*UU

// Tiling
#define BM 128
#define BN 256
#define BK 64            // fp16 elements per K-chunk (=128 bytes/row, SW128 atom)
#define NCHUNK (DD / BK) // 8
#define THREADS 256

// SMEM layout (relative to a 1024-aligned base inside dynamic smem)
#define SM_TMEM   0
#define SM_MBAR0  8
#define SM_MBAR1  16
#define SM_BIAS   1024                 // 256 floats
#define SM_A0     2048                 // 128 rows x 128B = 16384 B (fp16)
#define SM_A1     (SM_A0 + 16384)      // 18432
#define SM_B0     (SM_A1 + 16384)      // 34816 (1024-aligned), 256 rows x 128B = 32768 B
#define SM_B1     (SM_B0 + 32768)      // 67584
#define SM_END    (SM_B1 + 32768)      // 100352
#define SMEM_DYN  (SM_END + 1024)      // ~99 KB -> 2 CTAs/SM

// tcgen05 only exists on the arch-specific target (sm_103a). The harness's
// nvcc also runs a generic compute_103 PTX pass; give that pass a SIMT
// fallback body so ptxas doesn't abort. At runtime the sm_103a cubin is used.
#if !defined(__CUDA_ARCH__) || defined(__CUDA_ARCH_FEAT_SM103_ALL) || \
    defined(__CUDA_ARCH_SPECIFIC__) || defined(__CUDA_ARCH_FAMILY_SPECIFIC__)
#define HAS_TCGEN05 1
#else
#define HAS_TCGEN05 0
#endif

// SW128 K-major smem descriptor base: layout=SW128(2), version=1(Blackwell), SBO=64, LBO=1
static constexpr unsigned long long DESC_BASE =
    (2ULL << 61) | (1ULL << 46) | (64ULL << 32) | (1ULL << 16);

// idesc for kind::f16 (fp16 in, fp32 accum): c=F32(1@[4]), a=F16(0@[7]), b=F16(0@[10]),
// N=256(32@[17]), M=128(8@[24])
#define IDESC ((1u << 4) | (0u << 7) | (0u << 10) | (32u << 17) | (8u << 24))

// W pre-converted to fp16 (RN) once per call: [V, D] halves, stored as u32 pairs
__device__ uint32_t g_wh[VV * DD / 2];

// ---------------- inline PTX helpers ----------------

__device__ __forceinline__ uint32_t cvta_shared_u32(const void* p) {
    uint32_t a;
    asm("{ .reg .u64 t; cvta.to.shared.u64 t, %1; cvt.u32.u64 %0, t; }" : "=r"(a) : "l"(p));
    return a;
}

// pack two fp32 -> f16x2 {lo, hi}
__device__ __forceinline__ uint32_t pack_f16x2(float lo, float hi) {
    uint32_t r;
    asm("cvt.rn.f16x2.f32 %0, %1, %2;" : "=r"(r) : "f"(hi), "f"(lo));
    return r;
}

#if HAS_TCGEN05
__device__ __forceinline__ bool elect_one() {
    uint32_t p;
    asm volatile(
        "{ .reg .pred P; elect.sync _|P, 0xFFFFFFFF; selp.b32 %0, 1, 0, P; }" : "=r"(p));
    return p != 0;
}

__device__ __forceinline__ void mbar_wait(uint32_t addr, uint32_t parity) {
    asm volatile(
        "{\n\t.reg .pred P;\n\t"
        "WL%=:\n\t"
        "mbarrier.try_wait.parity.acquire.cta.shared::cta.b64 P, [%0], %1, 0x989680;\n\t"
        "@P bra.uni WD%=;\n\t"
        "bra.uni WL%=;\n\t"
        "WD%=:\n\t}"
        :: "r"(addr), "r"(parity) : "memory");
}

__device__ __forceinline__ void mma_f16(uint32_t d_tmem, uint64_t a_desc, uint64_t b_desc,
                                        uint32_t idesc, uint32_t en) {
    asm volatile(
        "{\n\t.reg .pred p;\n\t"
        "setp.ne.u32 p, %5, 0;\n\t"
        "tcgen05.mma.cta_group::1.kind::f16 [%0], %1, %2, %3, {%4, %4, %4, %4}, p;\n\t}"
        :: "r"(d_tmem), "l"(a_desc), "l"(b_desc), "r"(idesc), "r"(0u), "r"(en)
        : "memory");
}

__device__ __forceinline__ void cp_async16(uint32_t dst, const void* src) {
    asm volatile("cp.async.cg.shared.global [%0], [%1], 16;"
                 :: "r"(dst), "l"(src) : "memory");
}
#endif // HAS_TCGEN05

// ---------------- main kernel ----------------

__global__ void __launch_bounds__(THREADS, 2)
joiner_f16_kernel(const float* __restrict__ src,   // [B,T,D]
                  const float* __restrict__ tgt,   // [B,U,D]
                  const float* __restrict__ bias,  // [V]
                  float* __restrict__ out)         // [M_TOTAL, V]
{
#if HAS_TCGEN05
    extern __shared__ char smem_raw[];
    uint32_t sb = (cvta_shared_u32(smem_raw) + 1023u) & ~1023u;

    const int tid = threadIdx.x;
    const int wid = tid >> 5;
    const int lid = tid & 31;
    const int m0 = blockIdx.y * BM;
    const int n0 = blockIdx.x * BN;

    if (tid == 0) {
        asm volatile("mbarrier.init.shared.b64 [%0], 1;" :: "r"(sb + SM_MBAR0) : "memory");
        asm volatile("mbarrier.init.shared.b64 [%0], 1;" :: "r"(sb + SM_MBAR1) : "memory");
    }
    if (wid == 0) {
        asm volatile("tcgen05.alloc.cta_group::1.sync.aligned.shared::cta.b32 [%0], %1;"
                     :: "r"(sb + SM_TMEM), "r"(256u) : "memory");
        asm volatile("tcgen05.relinquish_alloc_permit.cta_group::1.sync.aligned;");
    }
    {   // bias tile: 256 floats
        float b0 = bias[n0 + tid];
        asm volatile("st.shared.f32 [%0], %1;" :: "r"(sb + SM_BIAS + tid * 4), "f"(b0));
    }

    // ---- hoisted per-thread addressing ----
    const int r0 = tid >> 3;          // row-within-32 (0..31)
    const int j8 = tid & 7;           // 16-byte (8×fp16) column group
    uint32_t swBase = (uint32_t)((r0 << 7) + (j8 << 4));
    swBase ^= (swBase >> 3) & 0x70;   // SW128 (invariant under +32-row steps)

    // A rows r0+32s (s=0..3): decode (b,t,u) once; chunk c adds c*BK floats
    const float* sp[4];
    const float* tp[4];
#pragma unroll
    for (int s = 0; s < 4; ++s) {
        int m = m0 + r0 + 32 * s;
        int bi = m >> 14, ti = (m >> 6) & 255, ui = m & 63;
        sp[s] = src + (size_t)(bi * TT + ti) * DD + j8 * 8;
        tp[s] = tgt + (size_t)(bi * UU + ui) * DD + j8 * 8;
    }
    // B rows n0+r0+32s (s=0..7): fp16, chunk c adds c*128 bytes
    const char* bp = (const char*)g_wh + ((size_t)(n0 + r0) * DD + j8 * 8) * 2;

    __syncthreads();

    uint32_t tmem;
    asm volatile("ld.shared.b32 %0, [%1];" : "=r"(tmem) : "r"(sb + SM_TMEM));

    const uint64_t dA0 = DESC_BASE | ((uint64_t)((sb + SM_A0) >> 4) & 0x3FFF);
    const uint64_t dA1 = DESC_BASE | ((uint64_t)((sb + SM_A1) >> 4) & 0x3FFF);
    const uint64_t dB0 = DESC_BASE | ((uint64_t)((sb + SM_B0) >> 4) & 0x3FFF);
    const uint64_t dB1 = DESC_BASE | ((uint64_t)((sb + SM_B1) >> 4) & 0x3FFF);

    // fill buffer `bf` with chunk `c` (B via cp.async + commit, A via STS)
    auto fill = [&](int c, int bf) {
        const uint32_t aB = sb + (bf ? SM_A1 : SM_A0);
        const uint32_t bB = sb + (bf ? SM_B1 : SM_B0);
        const char* bpc = bp + (size_t)c * 128;
#pragma unroll
        for (int s = 0; s < 8; ++s) {
            cp_async16(bB + swBase + s * 4096u, bpc + (size_t)s * 32 * DD * 2);
        }
        asm volatile("cp.async.commit_group;" ::: "memory");
#pragma unroll
        for (int s = 0; s < 4; ++s) {
            const float* spc = sp[s] + c * BK;
            const float* tpc = tp[s] + c * BK;
            const float4 sa = *reinterpret_cast<const float4*>(spc);
            const float4 sbv = *reinterpret_cast<const float4*>(spc + 4);
            const float4 ta = *reinterpret_cast<const float4*>(tpc);
            const float4 tb = *reinterpret_cast<const float4*>(tpc + 4);
            uint32_t x0 = pack_f16x2(fmaxf(sa.x + ta.x, 0.f), fmaxf(sa.y + ta.y, 0.f));
            uint32_t x1 = pack_f16x2(fmaxf(sa.z + ta.z, 0.f), fmaxf(sa.w + ta.w, 0.f));
            uint32_t x2 = pack_f16x2(fmaxf(sbv.x + tb.x, 0.f), fmaxf(sbv.y + tb.y, 0.f));
            uint32_t x3 = pack_f16x2(fmaxf(sbv.z + tb.z, 0.f), fmaxf(sbv.w + tb.w, 0.f));
            asm volatile("st.shared.v4.b32 [%0], {%1, %2, %3, %4};"
                         :: "r"(aB + swBase + s * 4096u), "r"(x0), "r"(x1), "r"(x2), "r"(x3));
        }
    };

    // ---- pipelined mainloop: fill chunk i+1 while MMA of chunk i runs ----
    fill(0, 0);

#pragma unroll 1
    for (int i = 0; i < NCHUNK; ++i) {
        const int buf = i & 1;

        if (i + 1 < NCHUNK) {
            // buf^1 was read by MMA of chunk i-1: wait its commit before refill
            if (i >= 1) mbar_wait(sb + SM_MBAR0 + (buf ^ 1) * 8, ((i - 1) >> 1) & 1);
            fill(i + 1, buf ^ 1);
        }

        if (i + 1 < NCHUNK) asm volatile("cp.async.wait_group 1;" ::: "memory");
        else                asm volatile("cp.async.wait_group 0;" ::: "memory");
        asm volatile("fence.proxy.async.shared::cta;" ::: "memory");
        __syncthreads();

        // ---- 4 MMAs (K=16 each), then commit this buffer's mbar ----
        if (wid == 0) {
            uint64_t da = buf ? dA1 : dA0;
            uint64_t db = buf ? dB1 : dB0;
            if (elect_one()) {
#pragma unroll
                for (int ks = 0; ks < 4; ++ks) {
                    uint32_t en = (i | ks) ? 1u : 0u;   // first MMA overwrites D
                    mma_f16(tmem, da + ks * 2, db + ks * 2, IDESC, en);
                }
                asm volatile(
                    "tcgen05.commit.cta_group::1.mbarrier::arrive::one.shared::cluster.b64 [%0];"
                    :: "r"(sb + SM_MBAR0 + buf * 8) : "memory");
            }
        }
    }

    // each buffer committed 4 times -> last commit parity 1
    mbar_wait(sb + SM_MBAR0, 1);
    mbar_wait(sb + SM_MBAR1, 1);
    asm volatile("tcgen05.fence::after_thread_sync;" ::: "memory");

    // ---- epilogue: TMEM -> +bias -> GMEM ----
    // warps 0-3 cols [0,128), warps 4-7 cols [128,256); rows = (wid&3)*32 + lid
    const int rowLane = (wid & 3) * 32 + lid;
    const int colHalf = (wid >> 2) * 128;
    float* orow = out + (size_t)(m0 + rowLane) * VV + n0;

#pragma unroll 1
    for (int itc = 0; itc < 4; ++itc) {
        int cb = colHalf + itc * 32;
        uint32_t d[32];
        asm volatile(
            "tcgen05.ld.sync.aligned.32x32b.x32.b32 "
            "{%0, %1, %2, %3, %4, %5, %6, %7, "
            " %8, %9, %10, %11, %12, %13, %14, %15, "
            " %16, %17, %18, %19, %20, %21, %22, %23, "
            " %24, %25, %26, %27, %28, %29, %30, %31}, [%32];"
            : "=r"(d[0]), "=r"(d[1]), "=r"(d[2]), "=r"(d[3]),
              "=r"(d[4]), "=r"(d[5]), "=r"(d[6]), "=r"(d[7]),
              "=r"(d[8]), "=r"(d[9]), "=r"(d[10]), "=r"(d[11]),
              "=r"(d[12]), "=r"(d[13]), "=r"(d[14]), "=r"(d[15]),
              "=r"(d[16]), "=r"(d[17]), "=r"(d[18]), "=r"(d[19]),
              "=r"(d[20]), "=r"(d[21]), "=r"(d[22]), "=r"(d[23]),
              "=r"(d[24]), "=r"(d[25]), "=r"(d[26]), "=r"(d[27]),
              "=r"(d[28]), "=r"(d[29]), "=r"(d[30]), "=r"(d[31])
            : "r"(tmem + cb));
        asm volatile("tcgen05.wait::ld.sync.aligned;" ::: "memory");

#pragma unroll
        for (int c = 0; c < 32; c += 4) {
            float4 bv;
            asm volatile("ld.shared.v4.f32 {%0, %1, %2, %3}, [%4];"
                         : "=f"(bv.x), "=f"(bv.y), "=f"(bv.z), "=f"(bv.w)
                         : "r"(sb + SM_BIAS + (cb + c) * 4));
            float4 v;
            v.x = __uint_as_float(d[c + 0]) + bv.x;
            v.y = __uint_as_float(d[c + 1]) + bv.y;
            v.z = __uint_as_float(d[c + 2]) + bv.z;
            v.w = __uint_as_float(d[c + 3]) + bv.w;
            *reinterpret_cast<float4*>(orow + cb + c) = v;
        }
    }

    __syncthreads();
    if (wid == 0) {
        asm volatile("tcgen05.dealloc.cta_group::1.sync.aligned.b32 %0, %1;"
                     :: "r"(tmem), "r"(256u));
    }
#else
    // ---- generic-PTX fallback (compute_103 pass only; never runs on sm_103a) ----
    const int tid = threadIdx.x;
    const int m0 = blockIdx.y * BM;
    const int n0 = blockIdx.x * BN;
    for (int r = 0; r < BM; ++r) {
        int m = m0 + r;
        int bi = m >> 14, ti = (m >> 6) & 255, ui = m & 63;
        const float* spp = src + (size_t)(bi * TT + ti) * DD;
        const float* tpp = tgt + (size_t)(bi * UU + ui) * DD;
        for (int c = tid; c < BN; c += THREADS) {
            const __half* wp = reinterpret_cast<const __half*>(g_wh) + (size_t)(n0 + c) * DD;
            float acc = bias[n0 + c];
            for (int k = 0; k < DD; ++k)
                acc += fmaxf(spp[k] + tpp[k], 0.0f) * __half2float(wp[k]);
            out[(size_t)m * VV + n0 + c] = acc;
        }
    }
#endif
}

// Prep kernel: convert W -> fp16 (RN) into g_wh, and write the two length
// arrays (cast to float values — the harness compares the flat buffer as f32).
__global__ void prep_kernel(const float* __restrict__ Wm,
                            const int* __restrict__ sl, const int* __restrict__ tl,
                            float* __restrict__ tail_dst, int extra) {
    int idx = blockIdx.x * 256 + threadIdx.x;     // 131072 float4 groups
    const float4 w4 = *reinterpret_cast<const float4*>(Wm + (size_t)idx * 4);
    uint2 o;
    o.x = pack_f16x2(w4.x, w4.y);
    o.y = pack_f16x2(w4.z, w4.w);
    *reinterpret_cast<uint2*>(g_wh + (size_t)idx * 2) = o;

    if (blockIdx.x == 0) {
        int i = threadIdx.x;
        if (i < 8 && extra >= 8)                        tail_dst[i] = (float)sl[i];
        else if (i >= 8 && i < 16 && extra >= 16)       tail_dst[i] = (float)tl[i - 8];
    }
}

extern "C" void kernel_launch(void* const* d_in, const int* in_sizes, int n_in,
                              void* d_out, int out_size) {
    const float* src  = (const float*)d_in[0];
    const int*   slen = (const int*)d_in[1];
    const float* tgt  = (const float*)d_in[2];
    const int*   tlen = (const int*)d_in[3];
    const float* Wm   = (const float*)d_in[4];
    const float* bias = (const float*)d_in[5];
    float* out = (float*)d_out;

    long long extra = (long long)out_size - (long long)M_TOTAL * VV;
    int extra_c = (int)(extra < 0 ? 0 : (extra > 16 ? 16 : extra));
    prep_kernel<<<VV * DD / 1024, 256>>>(Wm, slen, tlen,
                                         (float*)d_out + (long long)M_TOTAL * VV, extra_c);

    cudaFuncSetAttribute(joiner_f16_kernel,
                         cudaFuncAttributeMaxDynamicSharedMemorySize, SMEM_DYN);
    dim3 grid(VV / BN, M_TOTAL / BM);  // (4, 1024)
    joiner_f16_kernel<<<grid, THREADS, SMEM_DYN>>>(src, tgt, bias, out);
}

// round 11
// speedup vs baseline: 1.4456x; 1.0965x over previous
#include <cuda_runtime.h>
#include <cuda_fp16.h>
#include <cstdint>

// Problem constants
#define BB 8
#define TT 256
#define UU 64
#define DD 512
#define VV 1024
#define M_TOTAL 131072   // BB*TT*UU

// Tiling: each CTA owns BM m-rows and ALL of V, in 4 n-passes of 256.
#define BM 128
#define BN 256
#define BK 64            // fp16 elements per K-chunk (=128 bytes/row, SW128 atom)
#define NCHUNK (DD / BK) // 8
#define NPASS (VV / BN)  // 4
#define NSTEP (NCHUNK * NPASS) // 32
#define THREADS 256

// SMEM layout
#define SM_TMEM   0
#define SM_MBAR0  8
#define SM_MBAR1  16
#define SM_BIAS   1024                   // 1024 floats = 4096 B
#define SM_A      6144                   // 8 slabs x 16384 = 131072 B (full-K A tile)
#define SM_B0     (SM_A + 131072)        // 137216 (1024-aligned)
#define SM_B1     (SM_B0 + 32768)        // 169984
#define SM_END    (SM_B1 + 32768)        // 202752
#define SMEM_DYN  (SM_END + 1024)        // ~199 KB -> 1 CTA/SM

#if !defined(__CUDA_ARCH__) || defined(__CUDA_ARCH_FEAT_SM103_ALL) || \
    defined(__CUDA_ARCH_SPECIFIC__) || defined(__CUDA_ARCH_FAMILY_SPECIFIC__)
#define HAS_TCGEN05 1
#else
#define HAS_TCGEN05 0
#endif

// SW128 K-major smem descriptor base: layout=SW128(2), version=1(Blackwell), SBO=64, LBO=1
static constexpr unsigned long long DESC_BASE =
    (2ULL << 61) | (1ULL << 46) | (64ULL << 32) | (1ULL << 16);

// idesc kind::f16 (fp16 in, fp32 accum): c=F32(1@[4]), a=F16, b=F16, N=256(32@[17]), M=128(8@[24])
#define IDESC ((1u << 4) | (32u << 17) | (8u << 24))

// W pre-converted to fp16 (RN) once per call
__device__ uint32_t g_wh[VV * DD / 2];

// ---------------- inline PTX helpers ----------------

__device__ __forceinline__ uint32_t cvta_shared_u32(const void* p) {
    uint32_t a;
    asm("{ .reg .u64 t; cvta.to.shared.u64 t, %1; cvt.u32.u64 %0, t; }" : "=r"(a) : "l"(p));
    return a;
}

__device__ __forceinline__ uint32_t pack_f16x2(float lo, float hi) {
    uint32_t r;
    asm("cvt.rn.f16x2.f32 %0, %1, %2;" : "=r"(r) : "f"(hi), "f"(lo));
    return r;
}

#if HAS_TCGEN05
__device__ __forceinline__ bool elect_one() {
    uint32_t p;
    asm volatile(
        "{ .reg .pred P; elect.sync _|P, 0xFFFFFFFF; selp.b32 %0, 1, 0, P; }" : "=r"(p));
    return p != 0;
}

__device__ __forceinline__ void mbar_wait(uint32_t addr, uint32_t parity) {
    asm volatile(
        "{\n\t.reg .pred P;\n\t"
        "WL%=:\n\t"
        "mbarrier.try_wait.parity.acquire.cta.shared::cta.b64 P, [%0], %1, 0x989680;\n\t"
        "@P bra.uni WD%=;\n\t"
        "bra.uni WL%=;\n\t"
        "WD%=:\n\t}"
        :: "r"(addr), "r"(parity) : "memory");
}

__device__ __forceinline__ void mma_f16(uint32_t d_tmem, uint64_t a_desc, uint64_t b_desc,
                                        uint32_t idesc, uint32_t en) {
    asm volatile(
        "{\n\t.reg .pred p;\n\t"
        "setp.ne.u32 p, %5, 0;\n\t"
        "tcgen05.mma.cta_group::1.kind::f16 [%0], %1, %2, %3, {%4, %4, %4, %4}, p;\n\t}"
        :: "r"(d_tmem), "l"(a_desc), "l"(b_desc), "r"(idesc), "r"(0u), "r"(en)
        : "memory");
}

__device__ __forceinline__ void cp_async16(uint32_t dst, const void* src) {
    asm volatile("cp.async.cg.shared.global [%0], [%1], 16;"
                 :: "r"(dst), "l"(src) : "memory");
}
#endif // HAS_TCGEN05

// ---------------- main kernel ----------------

__global__ void __launch_bounds__(THREADS, 1)
joiner_f16_kernel(const float* __restrict__ src,   // [B,T,D]
                  const float* __restrict__ tgt,   // [B,U,D]
                  const float* __restrict__ bias,  // [V]
                  float* __restrict__ out)         // [M_TOTAL, V]
{
#if HAS_TCGEN05
    extern __shared__ char smem_raw[];
    uint32_t sb = (cvta_shared_u32(smem_raw) + 1023u) & ~1023u;

    const int tid = threadIdx.x;
    const int wid = tid >> 5;
    const int lid = tid & 31;
    const int m0 = blockIdx.x * BM;

    if (tid == 0) {
        asm volatile("mbarrier.init.shared.b64 [%0], 1;" :: "r"(sb + SM_MBAR0) : "memory");
        asm volatile("mbarrier.init.shared.b64 [%0], 1;" :: "r"(sb + SM_MBAR1) : "memory");
    }
    if (wid == 0) {
        asm volatile("tcgen05.alloc.cta_group::1.sync.aligned.shared::cta.b32 [%0], %1;"
                     :: "r"(sb + SM_TMEM), "r"(256u) : "memory");
        asm volatile("tcgen05.relinquish_alloc_permit.cta_group::1.sync.aligned;");
    }
    // bias: all 1024 floats
#pragma unroll
    for (int k = 0; k < 4; ++k) {
        float bv = bias[tid + k * 256];
        asm volatile("st.shared.f32 [%0], %1;"
                     :: "r"(sb + SM_BIAS + (tid + k * 256) * 4), "f"(bv));
    }

    // ---- hoisted per-thread addressing ----
    const int r0 = tid >> 3;          // 0..31
    const int j8 = tid & 7;           // 16B (8 fp16) column group
    uint32_t swBase = (uint32_t)((r0 << 7) + (j8 << 4));
    swBase ^= (swBase >> 3) & 0x70;   // SW128 (invariant under +32-row steps)

    const float* sp[4];
    const float* tp[4];
#pragma unroll
    for (int s = 0; s < 4; ++s) {
        int m = m0 + r0 + 32 * s;
        int bi = m >> 14, ti = (m >> 6) & 255, ui = m & 63;
        sp[s] = src + (size_t)(bi * TT + ti) * DD + j8 * 8;
        tp[s] = tgt + (size_t)(bi * UU + ui) * DD + j8 * 8;
    }
    const char* bp = (const char*)g_wh + ((size_t)r0 * DD + j8 * 8) * 2;

    __syncthreads();

    uint32_t tmem;
    asm volatile("ld.shared.b32 %0, [%1];" : "=r"(tmem) : "r"(sb + SM_TMEM));

    const uint64_t dA = DESC_BASE | ((uint64_t)((sb + SM_A) >> 4) & 0x3FFF);
    const uint64_t dB0 = DESC_BASE | ((uint64_t)((sb + SM_B0) >> 4) & 0x3FFF);
    const uint64_t dB1 = DESC_BASE | ((uint64_t)((sb + SM_B1) >> 4) & 0x3FFF);

    // B fill for flattened step: pass = step>>3, chunk = step&7
    auto fill_b = [&](int step, int bf) {
        const uint32_t bB = sb + (bf ? SM_B1 : SM_B0);
        const int pass = step >> 3, chunk = step & 7;
        const char* base = bp + ((size_t)(pass * 256) * DD) * 2 + chunk * 128;
#pragma unroll
        for (int s = 0; s < 8; ++s) {
            cp_async16(bB + swBase + s * 4096u, base + (size_t)s * 32 * DD * 2);
        }
        asm volatile("cp.async.commit_group;" ::: "memory");
    };

    // kick off B chunk 0 before the (long) A build so the copy overlaps it
    fill_b(0, 0);

    // ---- A build: full K, once per m-tile -> 8 SW128 slabs ----
#pragma unroll 1
    for (int c = 0; c < NCHUNK; ++c) {
        const uint32_t aB = sb + SM_A + c * 16384u;
#pragma unroll
        for (int s = 0; s < 4; ++s) {
            const float* spc = sp[s] + c * BK;
            const float* tpc = tp[s] + c * BK;
            const float4 sa = *reinterpret_cast<const float4*>(spc);
            const float4 sbv = *reinterpret_cast<const float4*>(spc + 4);
            const float4 ta = *reinterpret_cast<const float4*>(tpc);
            const float4 tb = *reinterpret_cast<const float4*>(tpc + 4);
            uint32_t x0 = pack_f16x2(fmaxf(sa.x + ta.x, 0.f), fmaxf(sa.y + ta.y, 0.f));
            uint32_t x1 = pack_f16x2(fmaxf(sa.z + ta.z, 0.f), fmaxf(sa.w + ta.w, 0.f));
            uint32_t x2 = pack_f16x2(fmaxf(sbv.x + tb.x, 0.f), fmaxf(sbv.y + tb.y, 0.f));
            uint32_t x3 = pack_f16x2(fmaxf(sbv.z + tb.z, 0.f), fmaxf(sbv.w + tb.w, 0.f));
            asm volatile("st.shared.v4.b32 [%0], {%1, %2, %3, %4};"
                         :: "r"(aB + swBase + s * 4096u), "r"(x0), "r"(x1), "r"(x2), "r"(x3));
        }
    }
    asm volatile("fence.proxy.async.shared::cta;" ::: "memory");
    __syncthreads();

    // epilogue for pass p: D (tmem cols 0..255) -> +bias -> out cols [p*256, p*256+256)
    const int rowLane = (wid & 3) * 32 + lid;
    const int colHalf = (wid >> 2) * 128;
    auto epilogue = [&](int p) {
        asm volatile("tcgen05.fence::after_thread_sync;" ::: "memory");
        float* orow = out + (size_t)(m0 + rowLane) * VV + p * 256;
#pragma unroll 1
        for (int itc = 0; itc < 4; ++itc) {
            int cb = colHalf + itc * 32;
            uint32_t d[32];
            asm volatile(
                "tcgen05.ld.sync.aligned.32x32b.x32.b32 "
                "{%0, %1, %2, %3, %4, %5, %6, %7, "
                " %8, %9, %10, %11, %12, %13, %14, %15, "
                " %16, %17, %18, %19, %20, %21, %22, %23, "
                " %24, %25, %26, %27, %28, %29, %30, %31}, [%32];"
                : "=r"(d[0]), "=r"(d[1]), "=r"(d[2]), "=r"(d[3]),
                  "=r"(d[4]), "=r"(d[5]), "=r"(d[6]), "=r"(d[7]),
                  "=r"(d[8]), "=r"(d[9]), "=r"(d[10]), "=r"(d[11]),
                  "=r"(d[12]), "=r"(d[13]), "=r"(d[14]), "=r"(d[15]),
                  "=r"(d[16]), "=r"(d[17]), "=r"(d[18]), "=r"(d[19]),
                  "=r"(d[20]), "=r"(d[21]), "=r"(d[22]), "=r"(d[23]),
                  "=r"(d[24]), "=r"(d[25]), "=r"(d[26]), "=r"(d[27]),
                  "=r"(d[28]), "=r"(d[29]), "=r"(d[30]), "=r"(d[31])
                : "r"(tmem + cb));
            asm volatile("tcgen05.wait::ld.sync.aligned;" ::: "memory");
#pragma unroll
            for (int c = 0; c < 32; c += 4) {
                float4 bv;
                asm volatile("ld.shared.v4.f32 {%0, %1, %2, %3}, [%4];"
                             : "=f"(bv.x), "=f"(bv.y), "=f"(bv.z), "=f"(bv.w)
                             : "r"(sb + SM_BIAS + (p * 256 + cb + c) * 4));
                float4 v;
                v.x = __uint_as_float(d[c + 0]) + bv.x;
                v.y = __uint_as_float(d[c + 1]) + bv.y;
                v.z = __uint_as_float(d[c + 2]) + bv.z;
                v.w = __uint_as_float(d[c + 3]) + bv.w;
                *reinterpret_cast<float4*>(orow + cb + c) = v;
            }
        }
        asm volatile("tcgen05.fence::before_thread_sync;" ::: "memory");
    };

    // ---- flattened mainloop: 32 steps (4 passes x 8 chunks) ----
#pragma unroll 1
    for (int step = 0; step < NSTEP; ++step) {
        const int buf = step & 1;
        const int chunk = step & 7;

        if (step + 1 < NSTEP) {
            if (step >= 1) mbar_wait(sb + SM_MBAR0 + (buf ^ 1) * 8, ((step - 1) >> 1) & 1);
            fill_b(step + 1, buf ^ 1);
        }

        // pass boundary: drain previous pass's D while next B chunks fly
        if (chunk == 0 && step > 0) epilogue((step >> 3) - 1);

        if (step + 1 < NSTEP) asm volatile("cp.async.wait_group 1;" ::: "memory");
        else                  asm volatile("cp.async.wait_group 0;" ::: "memory");
        asm volatile("fence.proxy.async.shared::cta;" ::: "memory");
        __syncthreads();

        if (wid == 0) {
            uint64_t da = dA + chunk * 1024;   // slab c at +16KB = 1024 x 16B
            uint64_t db = (buf ? dB1 : dB0);
            if (elect_one()) {
#pragma unroll
                for (int ks = 0; ks < 4; ++ks) {
                    uint32_t en = (chunk | ks) ? 1u : 0u;  // overwrite D at pass start
                    mma_f16(tmem, da + ks * 2, db + ks * 2, IDESC, en);
                }
                asm volatile(
                    "tcgen05.commit.cta_group::1.mbarrier::arrive::one.shared::cluster.b64 [%0];"
                    :: "r"(sb + SM_MBAR0 + buf * 8) : "memory");
            }
        }
    }

    // final pass: commit of step 31 went to mbar1, commit #15 -> parity 1
    mbar_wait(sb + SM_MBAR1, 1);
    epilogue(NPASS - 1);

    __syncthreads();
    if (wid == 0) {
        asm volatile("tcgen05.dealloc.cta_group::1.sync.aligned.b32 %0, %1;"
                     :: "r"(tmem), "r"(256u));
    }
#else
    // ---- generic-PTX fallback (compute_103 pass only; never runs on sm_103a) ----
    const int tid = threadIdx.x;
    const int m0 = blockIdx.x * BM;
    for (int r = 0; r < BM; ++r) {
        int m = m0 + r;
        int bi = m >> 14, ti = (m >> 6) & 255, ui = m & 63;
        const float* spp = src + (size_t)(bi * TT + ti) * DD;
        const float* tpp = tgt + (size_t)(bi * UU + ui) * DD;
        for (int c = tid; c < VV; c += THREADS) {
            const __half* wp = reinterpret_cast<const __half*>(g_wh) + (size_t)c * DD;
            float acc = bias[c];
            for (int k = 0; k < DD; ++k)
                acc += fmaxf(spp[k] + tpp[k], 0.0f) * __half2float(wp[k]);
            out[(size_t)m * VV + c] = acc;
        }
    }
#endif
}

// Prep: W -> fp16 (RN) into g_wh; lengths written as float VALUES into the tail.
__global__ void prep_kernel(const float* __restrict__ Wm,
                            const int* __restrict__ sl, const int* __restrict__ tl,
                            float* __restrict__ tail_dst, int extra) {
    int idx = blockIdx.x * 256 + threadIdx.x;     // 131072 float4 groups
    const float4 w4 = *reinterpret_cast<const float4*>(Wm + (size_t)idx * 4);
    uint2 o;
    o.x = pack_f16x2(w4.x, w4.y);
    o.y = pack_f16x2(w4.z, w4.w);
    *reinterpret_cast<uint2*>(g_wh + (size_t)idx * 2) = o;

    if (blockIdx.x == 0) {
        int i = threadIdx.x;
        if (i < 8 && extra >= 8)                        tail_dst[i] = (float)sl[i];
        else if (i >= 8 && i < 16 && extra >= 16)       tail_dst[i] = (float)tl[i - 8];
    }
}

extern "C" void kernel_launch(void* const* d_in, const int* in_sizes, int n_in,
                              void* d_out, int out_size) {
    const float* src  = (const float*)d_in[0];
    const int*   slen = (const int*)d_in[1];
    const float* tgt  = (const float*)d_in[2];
    const int*   tlen = (const int*)d_in[3];
    const float* Wm   = (const float*)d_in[4];
    const float* bias = (const float*)d_in[5];
    float* out = (float*)d_out;

    long long extra = (long long)out_size - (long long)M_TOTAL * VV;
    int extra_c = (int)(extra < 0 ? 0 : (extra > 16 ? 16 : extra));
    prep_kernel<<<VV * DD / 1024, 256>>>(Wm, slen, tlen,
                                         (float*)d_out + (long long)M_TOTAL * VV, extra_c);

    cudaFuncSetAttribute(joiner_f16_kernel,
                         cudaFuncAttributeMaxDynamicSharedMemorySize, SMEM_DYN);
    joiner_f16_kernel<<<M_TOTAL / BM, THREADS, SMEM_DYN>>>(src, tgt, bias, out);
}

// round 13
// speedup vs baseline: 1.4906x; 1.0311x over previous
#include <cuda_runtime.h>
#include <cuda_fp16.h>
#include <cstdint>

// Problem constants
#define BB 8
#define TT 256
#define UU 64
#define DD 512
#define VV 1024
#define M_TOTAL 131072   // BB*TT*UU

// Tiling: each CTA owns BM m-rows and ALL of V, in 4 n-passes of 256.
#define BM 128
#define BN 256
#define BK 64            // fp16 elements per K-chunk (=128 bytes/row, SW128 atom)
#define NCHUNK (DD / BK) // 8
#define NPASS (VV / BN)  // 4
#define NSTEP (NCHUNK * NPASS) // 32
#define NSTAGE 3
#define THREADS 288      // warps 0-7 producers/epilogue, warp 8 MMA

// SMEM layout (relative to 1024-aligned base)
#define SM_TMEM   0
#define SM_FULL(s)  (8 + (s) * 8)     // 8,16,24
#define SM_EMPTY(s) (32 + (s) * 8)    // 32,40,48
#define SM_EPI    56
#define SM_A      1024                 // 8 slabs x 16384 = 131072
#define SM_B(s)   (132096 + (s) * 32768)
#define SM_END    (132096 + NSTAGE * 32768)   // 230400
#define SMEM_DYN  (SM_END + 1024)             // 231424 <= 232448 max

#if !defined(__CUDA_ARCH__) || defined(__CUDA_ARCH_FEAT_SM103_ALL) || \
    defined(__CUDA_ARCH_SPECIFIC__) || defined(__CUDA_ARCH_FAMILY_SPECIFIC__)
#define HAS_TCGEN05 1
#else
#define HAS_TCGEN05 0
#endif

// SW128 K-major smem descriptor base: layout=SW128(2), version=1(Blackwell), SBO=64, LBO=1
static constexpr unsigned long long DESC_BASE =
    (2ULL << 61) | (1ULL << 46) | (64ULL << 32) | (1ULL << 16);

// idesc kind::f16 (fp16 in, fp32 accum): c=F32(1@[4]), a=F16, b=F16, N=256(32@[17]), M=128(8@[24])
#define IDESC ((1u << 4) | (32u << 17) | (8u << 24))

// W pre-converted to fp16 (RN) once per call
__device__ uint32_t g_wh[VV * DD / 2];

// ---------------- inline PTX helpers ----------------

__device__ __forceinline__ uint32_t cvta_shared_u32(const void* p) {
    uint32_t a;
    asm("{ .reg .u64 t; cvta.to.shared.u64 t, %1; cvt.u32.u64 %0, t; }" : "=r"(a) : "l"(p));
    return a;
}

__device__ __forceinline__ uint32_t pack_f16x2(float lo, float hi) {
    uint32_t r;
    asm("cvt.rn.f16x2.f32 %0, %1, %2;" : "=r"(r) : "f"(hi), "f"(lo));
    return r;
}

#if HAS_TCGEN05
__device__ __forceinline__ bool elect_one() {
    uint32_t p;
    asm volatile(
        "{ .reg .pred P; elect.sync _|P, 0xFFFFFFFF; selp.b32 %0, 1, 0, P; }" : "=r"(p));
    return p != 0;
}

__device__ __forceinline__ void mbar_wait(uint32_t addr, uint32_t parity) {
    asm volatile(
        "{\n\t.reg .pred P;\n\t"
        "WL%=:\n\t"
        "mbarrier.try_wait.parity.acquire.cta.shared::cta.b64 P, [%0], %1, 0x989680;\n\t"
        "@P bra.uni WD%=;\n\t"
        "bra.uni WL%=;\n\t"
        "WD%=:\n\t}"
        :: "r"(addr), "r"(parity) : "memory");
}

__device__ __forceinline__ void mma_f16(uint32_t d_tmem, uint64_t a_desc, uint64_t b_desc,
                                        uint32_t idesc, uint32_t en) {
    asm volatile(
        "{\n\t.reg .pred p;\n\t"
        "setp.ne.u32 p, %5, 0;\n\t"
        "tcgen05.mma.cta_group::1.kind::f16 [%0], %1, %2, %3, {%4, %4, %4, %4}, p;\n\t}"
        :: "r"(d_tmem), "l"(a_desc), "l"(b_desc), "r"(idesc), "r"(0u), "r"(en)
        : "memory");
}

__device__ __forceinline__ void cp_async16(uint32_t dst, const void* src) {
    asm volatile("cp.async.cg.shared.global [%0], [%1], 16;"
                 :: "r"(dst), "l"(src) : "memory");
}

// .noinc: do NOT bump pending count — the barrier's init count already includes
// these arrives. (Default form is self-balancing: +1 then arrive = net zero,
// which made the FULL barriers never complete -> R12 deadlock.)
__device__ __forceinline__ void cp_async_arrive(uint32_t mbar) {
    asm volatile("cp.async.mbarrier.arrive.noinc.shared::cta.b64 [%0];"
                 :: "r"(mbar) : "memory");
}
#endif // HAS_TCGEN05

// ---------------- main kernel ----------------

__global__ void __launch_bounds__(THREADS, 1)
joiner_f16_kernel(const float* __restrict__ src,   // [B,T,D]
                  const float* __restrict__ tgt,   // [B,U,D]
                  const float* __restrict__ bias,  // [V]
                  float* __restrict__ out)         // [M_TOTAL, V]
{
#if HAS_TCGEN05
    extern __shared__ char smem_raw[];
    uint32_t sb = (cvta_shared_u32(smem_raw) + 1023u) & ~1023u;

    const int tid = threadIdx.x;
    const int wid = tid >> 5;
    const int lid = tid & 31;
    const int m0 = blockIdx.x * BM;

    if (tid == 0) {
#pragma unroll
        for (int s = 0; s < NSTAGE; ++s) {
            asm volatile("mbarrier.init.shared.b64 [%0], 256;" :: "r"(sb + SM_FULL(s)) : "memory");
            asm volatile("mbarrier.init.shared.b64 [%0], 1;"   :: "r"(sb + SM_EMPTY(s)) : "memory");
        }
        asm volatile("mbarrier.init.shared.b64 [%0], 256;" :: "r"(sb + SM_EPI) : "memory");
    }
    if (wid == 0) {
        asm volatile("tcgen05.alloc.cta_group::1.sync.aligned.shared::cta.b32 [%0], %1;"
                     :: "r"(sb + SM_TMEM), "r"(512u) : "memory");
        asm volatile("tcgen05.relinquish_alloc_permit.cta_group::1.sync.aligned;");
    }
    __syncthreads();   // mbar init + tmem alloc visible to everyone

    uint32_t tmem;
    asm volatile("ld.shared.b32 %0, [%1];" : "=r"(tmem) : "r"(sb + SM_TMEM));

    const uint64_t dA = DESC_BASE | ((uint64_t)((sb + SM_A) >> 4) & 0x3FFF);
    uint64_t dB[NSTAGE];
#pragma unroll
    for (int s = 0; s < NSTAGE; ++s)
        dB[s] = DESC_BASE | ((uint64_t)((sb + SM_B(s)) >> 4) & 0x3FFF);

    // ---- producer addressing (tid < 256) ----
    const int r0 = (tid & 255) >> 3;
    const int j8 = tid & 7;
    uint32_t swBase = (uint32_t)((r0 << 7) + (j8 << 4));
    swBase ^= (swBase >> 3) & 0x70;   // SW128

    const float* sp[4];
    const float* tp[4];
#pragma unroll
    for (int s = 0; s < 4; ++s) {
        int m = m0 + r0 + 32 * s;
        int bi = m >> 14, ti = (m >> 6) & 255, ui = m & 63;
        sp[s] = src + (size_t)(bi * TT + ti) * DD + j8 * 8;
        tp[s] = tgt + (size_t)(bi * UU + ui) * DD + j8 * 8;
    }
    const char* bp = (const char*)g_wh + ((size_t)r0 * DD + j8 * 8) * 2;

    // B fill for step t into stage st (issue only)
    auto fill_b = [&](int t, int st) {
        const uint32_t bB = sb + SM_B(st);
        const int pass = t >> 3, chunk = t & 7;
        const char* base = bp + ((size_t)(pass * 256) * DD) * 2 + chunk * 128;
#pragma unroll
        for (int s = 0; s < 8; ++s)
            cp_async16(bB + swBase + s * 4096u, base + (size_t)s * 32 * DD * 2);
    };

    // epilogue for pass p: D (tmem half p&1) -> +bias -> out cols [p*256, p*256+256)
    const int rowLane = (wid & 3) * 32 + lid;
    const int colHalf = (wid >> 2) * 128;
    auto epilogue = [&](int p) {
        asm volatile("tcgen05.fence::after_thread_sync;" ::: "memory");
        float* orow = out + (size_t)(m0 + rowLane) * VV + p * 256;
        const float* bcol = bias + p * 256;
        uint32_t tbase = tmem + (p & 1) * 256;
#pragma unroll 1
        for (int itc = 0; itc < 4; ++itc) {
            int cb = colHalf + itc * 32;
            uint32_t d[32];
            asm volatile(
                "tcgen05.ld.sync.aligned.32x32b.x32.b32 "
                "{%0, %1, %2, %3, %4, %5, %6, %7, "
                " %8, %9, %10, %11, %12, %13, %14, %15, "
                " %16, %17, %18, %19, %20, %21, %22, %23, "
                " %24, %25, %26, %27, %28, %29, %30, %31}, [%32];"
                : "=r"(d[0]), "=r"(d[1]), "=r"(d[2]), "=r"(d[3]),
                  "=r"(d[4]), "=r"(d[5]), "=r"(d[6]), "=r"(d[7]),
                  "=r"(d[8]), "=r"(d[9]), "=r"(d[10]), "=r"(d[11]),
                  "=r"(d[12]), "=r"(d[13]), "=r"(d[14]), "=r"(d[15]),
                  "=r"(d[16]), "=r"(d[17]), "=r"(d[18]), "=r"(d[19]),
                  "=r"(d[20]), "=r"(d[21]), "=r"(d[22]), "=r"(d[23]),
                  "=r"(d[24]), "=r"(d[25]), "=r"(d[26]), "=r"(d[27]),
                  "=r"(d[28]), "=r"(d[29]), "=r"(d[30]), "=r"(d[31])
                : "r"(tbase + cb));
            asm volatile("tcgen05.wait::ld.sync.aligned;" ::: "memory");
#pragma unroll
            for (int c = 0; c < 32; c += 4) {
                const float4 bv = __ldg(reinterpret_cast<const float4*>(bcol + cb + c));
                float4 v;
                v.x = __uint_as_float(d[c + 0]) + bv.x;
                v.y = __uint_as_float(d[c + 1]) + bv.y;
                v.z = __uint_as_float(d[c + 2]) + bv.z;
                v.w = __uint_as_float(d[c + 3]) + bv.w;
                *reinterpret_cast<float4*>(orow + cb + c) = v;
            }
        }
        asm volatile("tcgen05.fence::before_thread_sync;" ::: "memory");
    };

    if (wid < 8) {
        // ---- prefill stages 0..2 (issue before A build so copies overlap it) ----
#pragma unroll
        for (int s = 0; s < NSTAGE; ++s) fill_b(s, s);

        // ---- A build: full K, once ----
#pragma unroll 1
        for (int c = 0; c < NCHUNK; ++c) {
            const uint32_t aB = sb + SM_A + c * 16384u;
#pragma unroll
            for (int s = 0; s < 4; ++s) {
                const float* spc = sp[s] + c * BK;
                const float* tpc = tp[s] + c * BK;
                const float4 sa = *reinterpret_cast<const float4*>(spc);
                const float4 sbv = *reinterpret_cast<const float4*>(spc + 4);
                const float4 ta = *reinterpret_cast<const float4*>(tpc);
                const float4 tb = *reinterpret_cast<const float4*>(tpc + 4);
                uint32_t x0 = pack_f16x2(fmaxf(sa.x + ta.x, 0.f), fmaxf(sa.y + ta.y, 0.f));
                uint32_t x1 = pack_f16x2(fmaxf(sa.z + ta.z, 0.f), fmaxf(sa.w + ta.w, 0.f));
                uint32_t x2 = pack_f16x2(fmaxf(sbv.x + tb.x, 0.f), fmaxf(sbv.y + tb.y, 0.f));
                uint32_t x3 = pack_f16x2(fmaxf(sbv.z + tb.z, 0.f), fmaxf(sbv.w + tb.w, 0.f));
                asm volatile("st.shared.v4.b32 [%0], {%1, %2, %3, %4};"
                             :: "r"(aB + swBase + s * 4096u), "r"(x0), "r"(x1), "r"(x2), "r"(x3));
            }
        }
        asm volatile("fence.proxy.async.shared::cta;" ::: "memory");
    }
    __syncthreads();   // A visible; prefill cp.asyncs issued

    if (wid == 8) {
        // ================= MMA warp =================
#pragma unroll 1
        for (int t = 0; t < NSTEP; ++t) {
            const int s = t % 3;
            const int chunk = t & 7;
            const int half = (t >> 3) & 1;
            // epilogue-done guard before reusing a TMEM half (passes 2,3)
            if (t == 16) mbar_wait(sb + SM_EPI, 0);
            if (t == 24) mbar_wait(sb + SM_EPI, 1);
            mbar_wait(sb + SM_FULL(s), (t / 3) & 1);
            asm volatile("fence.proxy.async.shared::cta;" ::: "memory");
            if (elect_one()) {
#pragma unroll
                for (int ks = 0; ks < 4; ++ks) {
                    uint32_t en = (chunk | ks) ? 1u : 0u;
                    mma_f16(tmem + half * 256, dA + chunk * 1024 + ks * 2,
                            dB[s] + ks * 2, IDESC, en);
                }
                asm volatile(
                    "tcgen05.commit.cta_group::1.mbarrier::arrive::one.shared::cluster.b64 [%0];"
                    :: "r"(sb + SM_EMPTY(s)) : "memory");
            }
        }
    } else {
        // ================= producers + epilogue =================
        // signal prefilled stages (arrive fires when this thread's cp.asyncs land)
        cp_async_arrive(sb + SM_FULL(0));
        cp_async_arrive(sb + SM_FULL(1));
        cp_async_arrive(sb + SM_FULL(2));

#pragma unroll 1
        for (int t = NSTAGE; t < NSTEP; ++t) {
            const int s = t % 3;
            // wait MMA of step t-3 (which used stage s) to finish
            mbar_wait(sb + SM_EMPTY(s), ((t - 3) / 3) & 1);
            fill_b(t, s);
            cp_async_arrive(sb + SM_FULL(s));
            // pass boundaries: at t = 10+8p the wait above confirmed MMA step 8p+7 done
            if (t == 10 || t == 18 || t == 26) {
                epilogue((t - 10) >> 3);
                asm volatile("mbarrier.arrive.shared::cta.b64 _, [%0];"
                             :: "r"(sb + SM_EPI) : "memory");
            }
        }
        // final pass: wait MMA step 31 (stage 1, parity (31/3)&1 = 0)
        mbar_wait(sb + SM_EMPTY(1), 0);
        epilogue(NPASS - 1);
    }

    __syncthreads();
    if (wid == 0) {
        asm volatile("tcgen05.dealloc.cta_group::1.sync.aligned.b32 %0, %1;"
                     :: "r"(tmem), "r"(512u));
    }
#else
    // ---- generic-PTX fallback (compute_103 pass only; never runs on sm_103a) ----
    const int tid = threadIdx.x;
    const int m0 = blockIdx.x * BM;
    for (int r = 0; r < BM; ++r) {
        int m = m0 + r;
        int bi = m >> 14, ti = (m >> 6) & 255, ui = m & 63;
        const float* spp = src + (size_t)(bi * TT + ti) * DD;
        const float* tpp = tgt + (size_t)(bi * UU + ui) * DD;
        for (int c = tid; c < VV; c += THREADS) {
            const __half* wp = reinterpret_cast<const __half*>(g_wh) + (size_t)c * DD;
            float acc = bias[c];
            for (int k = 0; k < DD; ++k)
                acc += fmaxf(spp[k] + tpp[k], 0.0f) * __half2float(wp[k]);
            out[(size_t)m * VV + c] = acc;
        }
    }
#endif
}

// Prep: W -> fp16 (RN) into g_wh; lengths written as float VALUES into the tail.
__global__ void prep_kernel(const float* __restrict__ Wm,
                            const int* __restrict__ sl, const int* __restrict__ tl,
                            float* __restrict__ tail_dst, int extra) {
    int idx = blockIdx.x * 256 + threadIdx.x;     // 131072 float4 groups
    const float4 w4 = *reinterpret_cast<const float4*>(Wm + (size_t)idx * 4);
    uint2 o;
    o.x = pack_f16x2(w4.x, w4.y);
    o.y = pack_f16x2(w4.z, w4.w);
    *reinterpret_cast<uint2*>(g_wh + (size_t)idx * 2) = o;

    if (blockIdx.x == 0) {
        int i = threadIdx.x;
        if (i < 8 && extra >= 8)                        tail_dst[i] = (float)sl[i];
        else if (i >= 8 && i < 16 && extra >= 16)       tail_dst[i] = (float)tl[i - 8];
    }
}

extern "C" void kernel_launch(void* const* d_in, const int* in_sizes, int n_in,
                              void* d_out, int out_size) {
    const float* src  = (const float*)d_in[0];
    const int*   slen = (const int*)d_in[1];
    const float* tgt  = (const float*)d_in[2];
    const int*   tlen = (const int*)d_in[3];
    const float* Wm   = (const float*)d_in[4];
    const float* bias = (const float*)d_in[5];
    float* out = (float*)d_out;

    long long extra = (long long)out_size - (long long)M_TOTAL * VV;
    int extra_c = (int)(extra < 0 ? 0 : (extra > 16 ? 16 : extra));
    prep_kernel<<<VV * DD / 1024, 256>>>(Wm, slen, tlen,
                                         (float*)d_out + (long long)M_TOTAL * VV, extra_c);

    cudaFuncSetAttribute(joiner_f16_kernel,
                         cudaFuncAttributeMaxDynamicSharedMemorySize, SMEM_DYN);
    joiner_f16_kernel<<<M_TOTAL / BM, THREADS, SMEM_DYN>>>(src, tgt, bias, out);
}

// round 14
// speedup vs baseline: 1.5737x; 1.0558x over previous
#include <cuda_runtime.h>
#include <cuda_fp16.h>
#include <cuda.h>
#include <cstdint>

// Problem constants
#define BB 8
#define TT 256
#define UU 64
#define DD 512
#define VV 1024
#define M_TOTAL 131072   // BB*TT*UU

// Tiling: each CTA owns BM m-rows and ALL of V, in 4 n-passes of 256.
#define BM 128
#define BN 256
#define BK 64            // fp16 per K-chunk (=128 bytes/row, SW128 atom)
#define NCHUNK (DD / BK) // 8
#define NPASS (VV / BN)  // 4
#define NSTEP (NCHUNK * NPASS) // 32
#define NSTAGE 3
#define B_TILE_BYTES 32768
#define THREADS 288      // warps 0-7 A-build/epilogue, warp 8 TMA+MMA

// SMEM layout (relative to 1024-aligned base)
#define SM_TMEM   0
#define SM_FULL(s)  (8 + (s) * 8)     // 8,16,24
#define SM_EMPTY(s) (32 + (s) * 8)    // 32,40,48
#define SM_EPI    56
#define SM_PASS0  64
#define SM_PASS1  72
#define SM_A      1024                 // 8 slabs x 16384 = 131072
#define SM_B(s)   (132096 + (s) * 32768)
#define SM_END    (132096 + NSTAGE * 32768)   // 230400
#define SMEM_DYN  (SM_END + 1024)             // 231424 <= 232448 max

#if !defined(__CUDA_ARCH__) || defined(__CUDA_ARCH_FEAT_SM103_ALL) || \
    defined(__CUDA_ARCH_SPECIFIC__) || defined(__CUDA_ARCH_FAMILY_SPECIFIC__)
#define HAS_TCGEN05 1
#else
#define HAS_TCGEN05 0
#endif

// SW128 K-major smem descriptor base: layout=SW128(2), version=1(Blackwell), SBO=64, LBO=1
static constexpr unsigned long long DESC_BASE =
    (2ULL << 61) | (1ULL << 46) | (64ULL << 32) | (1ULL << 16);

// idesc kind::f16 (fp16 in, fp32 accum): c=F32(1@[4]), a=F16, b=F16, N=256(32@[17]), M=128(8@[24])
#define IDESC ((1u << 4) | (32u << 17) | (8u << 24))

// W pre-converted to fp16 (RN) once per call: [V rows, D cols] fp16
__device__ uint32_t g_wh[VV * DD / 2];

// ---------------- inline PTX helpers ----------------

__device__ __forceinline__ uint32_t cvta_shared_u32(const void* p) {
    uint32_t a;
    asm("{ .reg .u64 t; cvta.to.shared.u64 t, %1; cvt.u32.u64 %0, t; }" : "=r"(a) : "l"(p));
    return a;
}

__device__ __forceinline__ uint32_t pack_f16x2(float lo, float hi) {
    uint32_t r;
    asm("cvt.rn.f16x2.f32 %0, %1, %2;" : "=r"(r) : "f"(hi), "f"(lo));
    return r;
}

#if HAS_TCGEN05
__device__ __forceinline__ void mbar_wait(uint32_t addr, uint32_t parity) {
    asm volatile(
        "{\n\t.reg .pred P;\n\t"
        "WL%=:\n\t"
        "mbarrier.try_wait.parity.acquire.cta.shared::cta.b64 P, [%0], %1, 0x989680;\n\t"
        "@P bra.uni WD%=;\n\t"
        "bra.uni WL%=;\n\t"
        "WD%=:\n\t}"
        :: "r"(addr), "r"(parity) : "memory");
}

__device__ __forceinline__ void mma_f16(uint32_t d_tmem, uint64_t a_desc, uint64_t b_desc,
                                        uint32_t idesc, uint32_t en) {
    asm volatile(
        "{\n\t.reg .pred p;\n\t"
        "setp.ne.u32 p, %5, 0;\n\t"
        "tcgen05.mma.cta_group::1.kind::f16 [%0], %1, %2, %3, {%4, %4, %4, %4}, p;\n\t}"
        :: "r"(d_tmem), "l"(a_desc), "l"(b_desc), "r"(idesc), "r"(0u), "r"(en)
        : "memory");
}

__device__ __forceinline__ void tma_load_2d(uint32_t dst, const void* map,
                                            int x, int y, uint32_t mbar) {
    asm volatile(
        "cp.async.bulk.tensor.2d.shared::cta.global.tile.mbarrier::complete_tx::bytes "
        "[%0], [%1, {%2, %3}], [%4];"
        :: "r"(dst), "l"(map), "r"(x), "r"(y), "r"(mbar) : "memory");
}

__device__ __forceinline__ void mbar_expect_tx(uint32_t mbar, uint32_t bytes) {
    asm volatile("mbarrier.arrive.expect_tx.shared.b64 _, [%0], %1;"
                 :: "r"(mbar), "r"(bytes) : "memory");
}
#endif // HAS_TCGEN05

// ---------------- main kernel ----------------

__global__ void __launch_bounds__(THREADS, 1)
joiner_f16_kernel(const float* __restrict__ src,   // [B,T,D]
                  const float* __restrict__ tgt,   // [B,U,D]
                  const float* __restrict__ bias,  // [V]
                  float* __restrict__ out,         // [M_TOTAL, V]
                  const __grid_constant__ CUtensorMap tmap)  // over g_wh [1024 x 512] fp16
{
#if HAS_TCGEN05
    extern __shared__ char smem_raw[];
    uint32_t sb = (cvta_shared_u32(smem_raw) + 1023u) & ~1023u;

    const int tid = threadIdx.x;
    const int wid = tid >> 5;
    const int lid = tid & 31;
    const int m0 = blockIdx.x * BM;

    if (tid == 0) {
#pragma unroll
        for (int s = 0; s < NSTAGE; ++s) {
            asm volatile("mbarrier.init.shared.b64 [%0], 1;" :: "r"(sb + SM_FULL(s)) : "memory");
            asm volatile("mbarrier.init.shared.b64 [%0], 1;" :: "r"(sb + SM_EMPTY(s)) : "memory");
        }
        asm volatile("mbarrier.init.shared.b64 [%0], 256;" :: "r"(sb + SM_EPI) : "memory");
        asm volatile("mbarrier.init.shared.b64 [%0], 1;"   :: "r"(sb + SM_PASS0) : "memory");
        asm volatile("mbarrier.init.shared.b64 [%0], 1;"   :: "r"(sb + SM_PASS1) : "memory");
    }
    if (wid == 0) {
        asm volatile("tcgen05.alloc.cta_group::1.sync.aligned.shared::cta.b32 [%0], %1;"
                     :: "r"(sb + SM_TMEM), "r"(512u) : "memory");
        asm volatile("tcgen05.relinquish_alloc_permit.cta_group::1.sync.aligned;");
    }
    __syncthreads();   // mbar init + tmem alloc visible

    uint32_t tmem;
    asm volatile("ld.shared.b32 %0, [%1];" : "=r"(tmem) : "r"(sb + SM_TMEM));

    const uint64_t dA = DESC_BASE | ((uint64_t)((sb + SM_A) >> 4) & 0x3FFF);
    uint64_t dB[NSTAGE];
#pragma unroll
    for (int s = 0; s < NSTAGE; ++s)
        dB[s] = DESC_BASE | ((uint64_t)((sb + SM_B(s)) >> 4) & 0x3FFF);

    // TMA fill: step t -> stage st. coords: x = chunk*64 (fp16), y = pass*256 (row)
    auto tma_fill = [&](int t, int st) {
        mbar_expect_tx(sb + SM_FULL(st), B_TILE_BYTES);
        tma_load_2d(sb + SM_B(st), &tmap, (t & 7) * BK, (t >> 3) * BN, sb + SM_FULL(st));
    };

    // ---- warp 8 elect: prefill 3 stages NOW (overlaps A build below) ----
    if (wid == 8 && lid == 0) {
#pragma unroll
        for (int s = 0; s < NSTAGE; ++s) tma_fill(s, s);
    }

    // ---- producers: A build (full K, once) ----
    const int r0 = (tid & 255) >> 3;
    const int j8 = tid & 7;
    uint32_t swBase = (uint32_t)((r0 << 7) + (j8 << 4));
    swBase ^= (swBase >> 3) & 0x70;   // SW128

    if (wid < 8) {
        const float* sp[4];
        const float* tp[4];
#pragma unroll
        for (int s = 0; s < 4; ++s) {
            int m = m0 + r0 + 32 * s;
            int bi = m >> 14, ti = (m >> 6) & 255, ui = m & 63;
            sp[s] = src + (size_t)(bi * TT + ti) * DD + j8 * 8;
            tp[s] = tgt + (size_t)(bi * UU + ui) * DD + j8 * 8;
        }
#pragma unroll 1
        for (int c = 0; c < NCHUNK; ++c) {
            const uint32_t aB = sb + SM_A + c * 16384u;
#pragma unroll
            for (int s = 0; s < 4; ++s) {
                const float* spc = sp[s] + c * BK;
                const float* tpc = tp[s] + c * BK;
                const float4 sa = *reinterpret_cast<const float4*>(spc);
                const float4 sbv = *reinterpret_cast<const float4*>(spc + 4);
                const float4 ta = *reinterpret_cast<const float4*>(tpc);
                const float4 tb = *reinterpret_cast<const float4*>(tpc + 4);
                uint32_t x0 = pack_f16x2(fmaxf(sa.x + ta.x, 0.f), fmaxf(sa.y + ta.y, 0.f));
                uint32_t x1 = pack_f16x2(fmaxf(sa.z + ta.z, 0.f), fmaxf(sa.w + ta.w, 0.f));
                uint32_t x2 = pack_f16x2(fmaxf(sbv.x + tb.x, 0.f), fmaxf(sbv.y + tb.y, 0.f));
                uint32_t x3 = pack_f16x2(fmaxf(sbv.z + tb.z, 0.f), fmaxf(sbv.w + tb.w, 0.f));
                asm volatile("st.shared.v4.b32 [%0], {%1, %2, %3, %4};"
                             :: "r"(aB + swBase + s * 4096u), "r"(x0), "r"(x1), "r"(x2), "r"(x3));
            }
        }
        asm volatile("fence.proxy.async.shared::cta;" ::: "memory");
    }
    __syncthreads();   // A visible to async proxy

    if (wid == 8) {
        // ================= TMA + MMA driver (single thread) =================
        if (lid == 0) {
#pragma unroll 1
            for (int t = 0; t < NSTEP; ++t) {
                // refill stage for step t+2 (needs commit of step t-1, same stage)
                if (t >= 1 && t + 2 < NSTEP) {
                    const int s2 = (t + 2) % 3;
                    mbar_wait(sb + SM_EMPTY(s2), ((t - 1) / 3) & 1);
                    tma_fill(t + 2, s2);
                }
                // TMEM half reuse guards
                if (t == 16) mbar_wait(sb + SM_EPI, 0);
                if (t == 24) mbar_wait(sb + SM_EPI, 1);

                const int s = t % 3;
                const int chunk = t & 7;
                const int half = (t >> 3) & 1;
                mbar_wait(sb + SM_FULL(s), (t / 3) & 1);
#pragma unroll
                for (int ks = 0; ks < 4; ++ks) {
                    uint32_t en = (chunk | ks) ? 1u : 0u;
                    mma_f16(tmem + half * 256, dA + chunk * 1024 + ks * 2,
                            dB[s] + ks * 2, IDESC, en);
                }
                asm volatile(
                    "tcgen05.commit.cta_group::1.mbarrier::arrive::one.shared::cluster.b64 [%0];"
                    :: "r"(sb + SM_EMPTY(s)) : "memory");
                // pass-end completion signals (alternating barriers: no parity aliasing)
                if (t == 7 || t == 23)
                    asm volatile(
                        "tcgen05.commit.cta_group::1.mbarrier::arrive::one.shared::cluster.b64 [%0];"
                        :: "r"(sb + SM_PASS0) : "memory");
                if (t == 15 || t == 31)
                    asm volatile(
                        "tcgen05.commit.cta_group::1.mbarrier::arrive::one.shared::cluster.b64 [%0];"
                        :: "r"(sb + SM_PASS1) : "memory");
            }
        }
    } else {
        // ================= epilogue warps =================
        const int rowLane = (wid & 3) * 32 + lid;
        const int colHalf = (wid >> 2) * 128;
        auto epilogue = [&](int p) {
            asm volatile("tcgen05.fence::after_thread_sync;" ::: "memory");
            float* orow = out + (size_t)(m0 + rowLane) * VV + p * 256;
            const float* bcol = bias + p * 256;
            uint32_t tbase = tmem + (p & 1) * 256;
#pragma unroll 1
            for (int itc = 0; itc < 4; ++itc) {
                int cb = colHalf + itc * 32;
                uint32_t d[32];
                asm volatile(
                    "tcgen05.ld.sync.aligned.32x32b.x32.b32 "
                    "{%0, %1, %2, %3, %4, %5, %6, %7, "
                    " %8, %9, %10, %11, %12, %13, %14, %15, "
                    " %16, %17, %18, %19, %20, %21, %22, %23, "
                    " %24, %25, %26, %27, %28, %29, %30, %31}, [%32];"
                    : "=r"(d[0]), "=r"(d[1]), "=r"(d[2]), "=r"(d[3]),
                      "=r"(d[4]), "=r"(d[5]), "=r"(d[6]), "=r"(d[7]),
                      "=r"(d[8]), "=r"(d[9]), "=r"(d[10]), "=r"(d[11]),
                      "=r"(d[12]), "=r"(d[13]), "=r"(d[14]), "=r"(d[15]),
                      "=r"(d[16]), "=r"(d[17]), "=r"(d[18]), "=r"(d[19]),
                      "=r"(d[20]), "=r"(d[21]), "=r"(d[22]), "=r"(d[23]),
                      "=r"(d[24]), "=r"(d[25]), "=r"(d[26]), "=r"(d[27]),
                      "=r"(d[28]), "=r"(d[29]), "=r"(d[30]), "=r"(d[31])
                    : "r"(tbase + cb));
                asm volatile("tcgen05.wait::ld.sync.aligned;" ::: "memory");
#pragma unroll
                for (int c = 0; c < 32; c += 4) {
                    const float4 bv = __ldg(reinterpret_cast<const float4*>(bcol + cb + c));
                    float4 v;
                    v.x = __uint_as_float(d[c + 0]) + bv.x;
                    v.y = __uint_as_float(d[c + 1]) + bv.y;
                    v.z = __uint_as_float(d[c + 2]) + bv.z;
                    v.w = __uint_as_float(d[c + 3]) + bv.w;
                    *reinterpret_cast<float4*>(orow + cb + c) = v;
                }
            }
            asm volatile("tcgen05.fence::before_thread_sync;" ::: "memory");
        };

        mbar_wait(sb + SM_PASS0, 0);  epilogue(0);
        asm volatile("mbarrier.arrive.shared::cta.b64 _, [%0];" :: "r"(sb + SM_EPI) : "memory");
        mbar_wait(sb + SM_PASS1, 0);  epilogue(1);
        asm volatile("mbarrier.arrive.shared::cta.b64 _, [%0];" :: "r"(sb + SM_EPI) : "memory");
        mbar_wait(sb + SM_PASS0, 1);  epilogue(2);
        mbar_wait(sb + SM_PASS1, 1);  epilogue(3);
    }

    __syncthreads();
    if (wid == 0) {
        asm volatile("tcgen05.dealloc.cta_group::1.sync.aligned.b32 %0, %1;"
                     :: "r"(tmem), "r"(512u));
    }
#else
    // ---- generic-PTX fallback (compute_103 pass only; never runs on sm_103a) ----
    const int tid = threadIdx.x;
    const int m0 = blockIdx.x * BM;
    for (int r = 0; r < BM; ++r) {
        int m = m0 + r;
        int bi = m >> 14, ti = (m >> 6) & 255, ui = m & 63;
        const float* spp = src + (size_t)(bi * TT + ti) * DD;
        const float* tpp = tgt + (size_t)(bi * UU + ui) * DD;
        for (int c = tid; c < VV; c += THREADS) {
            const __half* wp = reinterpret_cast<const __half*>(g_wh) + (size_t)c * DD;
            float acc = bias[c];
            for (int k = 0; k < DD; ++k)
                acc += fmaxf(spp[k] + tpp[k], 0.0f) * __half2float(wp[k]);
            out[(size_t)m * VV + c] = acc;
        }
    }
#endif
}

// Prep: W -> fp16 (RN) into g_wh; lengths written as float VALUES into the tail.
__global__ void prep_kernel(const float* __restrict__ Wm,
                            const int* __restrict__ sl, const int* __restrict__ tl,
                            float* __restrict__ tail_dst, int extra) {
    int idx = blockIdx.x * 256 + threadIdx.x;     // 131072 float4 groups
    const float4 w4 = *reinterpret_cast<const float4*>(Wm + (size_t)idx * 4);
    uint2 o;
    o.x = pack_f16x2(w4.x, w4.y);
    o.y = pack_f16x2(w4.z, w4.w);
    *reinterpret_cast<uint2*>(g_wh + (size_t)idx * 2) = o;

    if (blockIdx.x == 0) {
        int i = threadIdx.x;
        if (i < 8 && extra >= 8)                        tail_dst[i] = (float)sl[i];
        else if (i >= 8 && i < 16 && extra >= 16)       tail_dst[i] = (float)tl[i - 8];
    }
}

// ---------------- host side ----------------

typedef CUresult (*PFN_encodeTiled_t)(
    CUtensorMap*, CUtensorMapDataType, cuuint32_t, void*,
    const cuuint64_t*, const cuuint64_t*, const cuuint32_t*, const cuuint32_t*,
    CUtensorMapInterleave, CUtensorMapSwizzle, CUtensorMapL2promotion,
    CUtensorMapFloatOOBfill);

extern "C" void kernel_launch(void* const* d_in, const int* in_sizes, int n_in,
                              void* d_out, int out_size) {
    const float* src  = (const float*)d_in[0];
    const int*   slen = (const int*)d_in[1];
    const float* tgt  = (const float*)d_in[2];
    const int*   tlen = (const int*)d_in[3];
    const float* Wm   = (const float*)d_in[4];
    const float* bias = (const float*)d_in[5];
    float* out = (float*)d_out;

    long long extra = (long long)out_size - (long long)M_TOTAL * VV;
    int extra_c = (int)(extra < 0 ? 0 : (extra > 16 ? 16 : extra));
    prep_kernel<<<VV * DD / 1024, 256>>>(Wm, slen, tlen,
                                         (float*)d_out + (long long)M_TOTAL * VV, extra_c);

    // Build tensormap over g_wh: [1024 rows, 512 fp16], box [64, 256], SW128
    static CUtensorMap tmap;
    static bool tmap_ready = false;
    if (!tmap_ready) {
        void* whp = nullptr;
        cudaGetSymbolAddress(&whp, g_wh);
        void* fn = nullptr;
        cudaDriverEntryPointQueryResult qres;
        cudaGetDriverEntryPoint("cuTensorMapEncodeTiled", &fn,
                                cudaEnableDefault, &qres);
        PFN_encodeTiled_t encode = (PFN_encodeTiled_t)fn;
        cuuint64_t dims[2]    = { DD, VV };          // inner: 512 fp16, outer: 1024 rows
        cuuint64_t strides[1] = { DD * 2 };          // 1024 B per row
        cuuint32_t box[2]     = { BK, BN };          // 64 fp16 (=128B), 256 rows
        cuuint32_t estr[2]    = { 1, 1 };
        encode(&tmap, CU_TENSOR_MAP_DATA_TYPE_FLOAT16, 2, whp,
               dims, strides, box, estr,
               CU_TENSOR_MAP_INTERLEAVE_NONE, CU_TENSOR_MAP_SWIZZLE_128B,
               CU_TENSOR_MAP_L2_PROMOTION_L2_128B, CU_TENSOR_MAP_FLOAT_OOB_FILL_NONE);
        tmap_ready = true;
    }

    cudaFuncSetAttribute(joiner_f16_kernel,
                         cudaFuncAttributeMaxDynamicSharedMemorySize, SMEM_DYN);
    joiner_f16_kernel<<<M_TOTAL / BM, THREADS, SMEM_DYN>>>(src, tgt, bias, out, tmap);
}

// round 15
// speedup vs baseline: 1.7548x; 1.1151x over previous
#include <cuda_runtime.h>
#include <cuda_fp16.h>
#include <cuda.h>
#include <cstdint>

// Problem constants
#define BB 8
#define TT 256
#define UU 64
#define DD 512
#define VV 1024
#define M_TOTAL 131072   // BB*TT*UU

// Tiling: each CTA owns BM m-rows and ALL of V: 8 passes of N=128, 8 K-chunks.
#define BM 128
#define BN 128
#define BK 64            // fp16 per K-chunk (=128 bytes/row, SW128 atom)
#define NCHUNK (DD / BK) // 8
#define NPASS (VV / BN)  // 8
#define NGROUP 16        // 4 steps (=4 chunks) per group
#define B_TILE 16384     // 128 rows x 128 B
#define SLOT_BYTES (4 * B_TILE)
#define THREADS 288      // warps 0-7 A-build/epilogue, warp 8 TMA+MMA driver

// TMEM layout: D0 cols 0..127, D1 cols 128..255, A cols 256..511
#define TM_D(h)  ((h) * 128)
#define TM_A     256

// SMEM layout (relative to 1024-aligned base)
#define SM_TMEM     0
#define SM_FULLG(s)  (8 + (s) * 8)     // 8,16,24
#define SM_EMPTYG(s) (32 + (s) * 8)    // 32,40,48
#define SM_EPI(i)    (56 + (i) * 8)    // 56,64
#define SM_PASS(i)   (72 + (i) * 8)    // 72,80
#define SM_B        1024               // 3 slots x 65536
#define SM_END      (SM_B + 3 * SLOT_BYTES)   // 197632
#define SMEM_DYN    (SM_END + 1024)

#if !defined(__CUDA_ARCH__) || defined(__CUDA_ARCH_FEAT_SM103_ALL) || \
    defined(__CUDA_ARCH_SPECIFIC__) || defined(__CUDA_ARCH_FAMILY_SPECIFIC__)
#define HAS_TCGEN05 1
#else
#define HAS_TCGEN05 0
#endif

// SW128 K-major smem descriptor base: layout=SW128(2), version=1(Blackwell), SBO=64, LBO=1
static constexpr unsigned long long DESC_BASE =
    (2ULL << 61) | (1ULL << 46) | (64ULL << 32) | (1ULL << 16);

// idesc kind::f16: c=F32(1@[4]), a=F16, b=F16, N=128(16@[17]), M=128(8@[24])
#define IDESC ((1u << 4) | (16u << 17) | (8u << 24))

// W pre-converted to fp16 (RN) once per call: [V rows, D cols] fp16
__device__ uint32_t g_wh[VV * DD / 2];

// ---------------- inline PTX helpers ----------------

__device__ __forceinline__ uint32_t cvta_shared_u32(const void* p) {
    uint32_t a;
    asm("{ .reg .u64 t; cvta.to.shared.u64 t, %1; cvt.u32.u64 %0, t; }" : "=r"(a) : "l"(p));
    return a;
}

__device__ __forceinline__ uint32_t pack_f16x2(float lo, float hi) {
    uint32_t r;
    asm("cvt.rn.f16x2.f32 %0, %1, %2;" : "=r"(r) : "f"(hi), "f"(lo));
    return r;
}

#if HAS_TCGEN05
__device__ __forceinline__ void mbar_wait(uint32_t addr, uint32_t parity) {
    asm volatile(
        "{\n\t.reg .pred P;\n\t"
        "WL%=:\n\t"
        "mbarrier.try_wait.parity.acquire.cta.shared::cta.b64 P, [%0], %1, 0x989680;\n\t"
        "@P bra.uni WD%=;\n\t"
        "bra.uni WL%=;\n\t"
        "WD%=:\n\t}"
        :: "r"(addr), "r"(parity) : "memory");
}

// TS-mode MMA: A operand from TMEM
__device__ __forceinline__ void mma_f16_ts(uint32_t d_tmem, uint32_t a_tmem, uint64_t b_desc,
                                           uint32_t idesc, uint32_t en) {
    asm volatile(
        "{\n\t.reg .pred p;\n\t"
        "setp.ne.u32 p, %5, 0;\n\t"
        "tcgen05.mma.cta_group::1.kind::f16 [%0], [%1], %2, %3, {%4, %4, %4, %4}, p;\n\t}"
        :: "r"(d_tmem), "r"(a_tmem), "l"(b_desc), "r"(idesc), "r"(0u), "r"(en)
        : "memory");
}

__device__ __forceinline__ void tma_load_2d(uint32_t dst, const void* map,
                                            int x, int y, uint32_t mbar) {
    asm volatile(
        "cp.async.bulk.tensor.2d.shared::cta.global.tile.mbarrier::complete_tx::bytes "
        "[%0], [%1, {%2, %3}], [%4];"
        :: "r"(dst), "l"(map), "r"(x), "r"(y), "r"(mbar) : "memory");
}

__device__ __forceinline__ void mbar_expect_tx(uint32_t mbar, uint32_t bytes) {
    asm volatile("mbarrier.arrive.expect_tx.shared.b64 _, [%0], %1;"
                 :: "r"(mbar), "r"(bytes) : "memory");
}

__device__ __forceinline__ void tmem_st_x32(uint32_t addr, const uint32_t* r) {
    asm volatile(
        "tcgen05.st.sync.aligned.32x32b.x32.b32 [%0], "
        "{%1, %2, %3, %4, %5, %6, %7, %8, "
        " %9, %10, %11, %12, %13, %14, %15, %16, "
        " %17, %18, %19, %20, %21, %22, %23, %24, "
        " %25, %26, %27, %28, %29, %30, %31, %32};"
        :: "r"(addr),
           "r"(r[0]), "r"(r[1]), "r"(r[2]), "r"(r[3]),
           "r"(r[4]), "r"(r[5]), "r"(r[6]), "r"(r[7]),
           "r"(r[8]), "r"(r[9]), "r"(r[10]), "r"(r[11]),
           "r"(r[12]), "r"(r[13]), "r"(r[14]), "r"(r[15]),
           "r"(r[16]), "r"(r[17]), "r"(r[18]), "r"(r[19]),
           "r"(r[20]), "r"(r[21]), "r"(r[22]), "r"(r[23]),
           "r"(r[24]), "r"(r[25]), "r"(r[26]), "r"(r[27]),
           "r"(r[28]), "r"(r[29]), "r"(r[30]), "r"(r[31])
        : "memory");
}
#endif // HAS_TCGEN05

// ---------------- main kernel ----------------

__global__ void __launch_bounds__(THREADS, 1)
joiner_f16_kernel(const float* __restrict__ src,   // [B,T,D]
                  const float* __restrict__ tgt,   // [B,U,D]
                  const float* __restrict__ bias,  // [V]
                  float* __restrict__ out,         // [M_TOTAL, V]
                  const __grid_constant__ CUtensorMap tmap)  // g_wh [1024 x 512] fp16
{
#if HAS_TCGEN05
    extern __shared__ char smem_raw[];
    uint32_t sb = (cvta_shared_u32(smem_raw) + 1023u) & ~1023u;

    const int tid = threadIdx.x;
    const int wid = tid >> 5;
    const int lid = tid & 31;
    const int m0 = blockIdx.x * BM;

    if (tid == 0) {
#pragma unroll
        for (int s = 0; s < 3; ++s) {
            asm volatile("mbarrier.init.shared.b64 [%0], 1;" :: "r"(sb + SM_FULLG(s)) : "memory");
            asm volatile("mbarrier.init.shared.b64 [%0], 1;" :: "r"(sb + SM_EMPTYG(s)) : "memory");
        }
        asm volatile("mbarrier.init.shared.b64 [%0], 256;" :: "r"(sb + SM_EPI(0)) : "memory");
        asm volatile("mbarrier.init.shared.b64 [%0], 256;" :: "r"(sb + SM_EPI(1)) : "memory");
        asm volatile("mbarrier.init.shared.b64 [%0], 1;"   :: "r"(sb + SM_PASS(0)) : "memory");
        asm volatile("mbarrier.init.shared.b64 [%0], 1;"   :: "r"(sb + SM_PASS(1)) : "memory");
    }
    if (wid == 0) {
        asm volatile("tcgen05.alloc.cta_group::1.sync.aligned.shared::cta.b32 [%0], %1;"
                     :: "r"(sb + SM_TMEM), "r"(512u) : "memory");
        asm volatile("tcgen05.relinquish_alloc_permit.cta_group::1.sync.aligned;");
    }
    __syncthreads();   // barriers + tmem alloc visible

    uint32_t tmem;
    asm volatile("ld.shared.b32 %0, [%1];" : "=r"(tmem) : "r"(sb + SM_TMEM));

    // prefill: group g tile q lives at slot (g%3), coords x=(chunk)*64, y=(pass)*128
    auto tma_fill_group = [&](int g) {
        const int slot = g % 3;
        mbar_expect_tx(sb + SM_FULLG(slot), SLOT_BYTES);
        const int p = g >> 1;
        const int cbase = (g & 1) * 4;
#pragma unroll
        for (int q = 0; q < 4; ++q)
            tma_load_2d(sb + SM_B + slot * SLOT_BYTES + q * B_TILE, &tmap,
                        (cbase + q) * BK, p * BN, sb + SM_FULLG(slot));
    };

    if (wid == 8 && lid == 0) {
#pragma unroll
        for (int g = 0; g < 3; ++g) tma_fill_group(g);
    }

    // ---- A build into TMEM (warps 0-7): row=(wid&3)*32+lid, col half=(wid>>2)*128 ----
    if (wid < 8) {
        const int r = (wid & 3) * 32 + lid;
        const int m = m0 + r;
        const int bi = m >> 14, ti = (m >> 6) & 255, ui = m & 63;
        const float* sprow = src + (size_t)(bi * TT + ti) * DD;
        const float* tprow = tgt + (size_t)(bi * UU + ui) * DD;
        const int kb0 = (wid >> 2) * 256;            // K-element base (0 or 256)
        const uint32_t warp_off = (uint32_t)(wid & 3) << 21;
#pragma unroll
        for (int b = 0; b < 4; ++b) {
            const int kb = kb0 + b * 64;             // 64 K elems -> 32 cols
            uint32_t a[32];
#pragma unroll
            for (int j = 0; j < 16; ++j) {
                const float4 s4 = *reinterpret_cast<const float4*>(sprow + kb + j * 4);
                const float4 t4 = *reinterpret_cast<const float4*>(tprow + kb + j * 4);
                a[2 * j + 0] = pack_f16x2(fmaxf(s4.x + t4.x, 0.f), fmaxf(s4.y + t4.y, 0.f));
                a[2 * j + 1] = pack_f16x2(fmaxf(s4.z + t4.z, 0.f), fmaxf(s4.w + t4.w, 0.f));
            }
            tmem_st_x32(tmem + TM_A + (kb0 >> 1) + b * 32 + warp_off, a);
        }
        asm volatile("tcgen05.wait::st.sync.aligned;" ::: "memory");
        asm volatile("tcgen05.fence::before_thread_sync;" ::: "memory");
    }
    __syncthreads();   // A in TMEM visible

    if (wid == 8) {
        if (lid == 0) {
            asm volatile("tcgen05.fence::after_thread_sync;" ::: "memory");
            // ================= group-driver =================
#pragma unroll 1
            for (int g = 0; g < NGROUP; ++g) {
                const int slot = g % 3;
                const int p = g >> 1;
                if (g >= 1) {
                    // stage-slot reuse: wait commit of group g-1, then refill group g+2
                    mbar_wait(sb + SM_EMPTYG((g - 1) % 3), ((g - 1) / 3) & 1);
                    if (g + 2 < NGROUP) tma_fill_group(g + 2);
                }
                if ((g & 1) == 0 && p >= 2) {
                    // D-half reuse: epilogue of pass p-2 must be done
                    mbar_wait(sb + SM_EPI(p & 1), ((p - 2) >> 1) & 1);
                    asm volatile("tcgen05.fence::after_thread_sync;" ::: "memory");
                }
                mbar_wait(sb + SM_FULLG(slot), (g / 3) & 1);

                const uint32_t dT = tmem + TM_D(p & 1);
#pragma unroll
                for (int q = 0; q < 4; ++q) {
                    const int c = (g & 1) * 4 + q;
                    const uint64_t db = DESC_BASE |
                        ((uint64_t)((sb + SM_B + slot * SLOT_BYTES + q * B_TILE) >> 4) & 0x3FFF);
                    const uint32_t aT = tmem + TM_A + c * 32;
#pragma unroll
                    for (int ks = 0; ks < 4; ++ks) {
                        uint32_t en = (c | ks) ? 1u : 0u;   // overwrite D at pass start
                        mma_f16_ts(dT, aT + ks * 8, db + ks * 2, IDESC, en);
                    }
                }
                asm volatile(
                    "tcgen05.commit.cta_group::1.mbarrier::arrive::one.shared::cluster.b64 [%0];"
                    :: "r"(sb + SM_EMPTYG(slot)) : "memory");
                if (g & 1)   // pass p complete
                    asm volatile(
                        "tcgen05.commit.cta_group::1.mbarrier::arrive::one.shared::cluster.b64 [%0];"
                        :: "r"(sb + SM_PASS(p & 1)) : "memory");
            }
        }
    } else {
        // ================= epilogue warps (0-7) =================
        const int rowLane = (wid & 3) * 32 + lid;
        const int colBase = (wid >> 2) * 64;
        float* orowBase = out + (size_t)(m0 + rowLane) * VV;
#pragma unroll 1
        for (int p = 0; p < NPASS; ++p) {
            mbar_wait(sb + SM_PASS(p & 1), (p >> 1) & 1);
            asm volatile("tcgen05.fence::after_thread_sync;" ::: "memory");
            float* orow = orowBase + p * BN;
            const float* bcol = bias + p * BN;
            const uint32_t tbase = tmem + TM_D(p & 1);
#pragma unroll
            for (int itc = 0; itc < 2; ++itc) {
                const int cb = colBase + itc * 32;
                uint32_t d[32];
                asm volatile(
                    "tcgen05.ld.sync.aligned.32x32b.x32.b32 "
                    "{%0, %1, %2, %3, %4, %5, %6, %7, "
                    " %8, %9, %10, %11, %12, %13, %14, %15, "
                    " %16, %17, %18, %19, %20, %21, %22, %23, "
                    " %24, %25, %26, %27, %28, %29, %30, %31}, [%32];"
                    : "=r"(d[0]), "=r"(d[1]), "=r"(d[2]), "=r"(d[3]),
                      "=r"(d[4]), "=r"(d[5]), "=r"(d[6]), "=r"(d[7]),
                      "=r"(d[8]), "=r"(d[9]), "=r"(d[10]), "=r"(d[11]),
                      "=r"(d[12]), "=r"(d[13]), "=r"(d[14]), "=r"(d[15]),
                      "=r"(d[16]), "=r"(d[17]), "=r"(d[18]), "=r"(d[19]),
                      "=r"(d[20]), "=r"(d[21]), "=r"(d[22]), "=r"(d[23]),
                      "=r"(d[24]), "=r"(d[25]), "=r"(d[26]), "=r"(d[27]),
                      "=r"(d[28]), "=r"(d[29]), "=r"(d[30]), "=r"(d[31])
                    : "r"(tbase + cb));
                asm volatile("tcgen05.wait::ld.sync.aligned;" ::: "memory");
#pragma unroll
                for (int c = 0; c < 32; c += 4) {
                    const float4 bv = __ldg(reinterpret_cast<const float4*>(bcol + cb + c));
                    float4 v;
                    v.x = __uint_as_float(d[c + 0]) + bv.x;
                    v.y = __uint_as_float(d[c + 1]) + bv.y;
                    v.z = __uint_as_float(d[c + 2]) + bv.z;
                    v.w = __uint_as_float(d[c + 3]) + bv.w;
                    *reinterpret_cast<float4*>(orow + cb + c) = v;
                }
            }
            asm volatile("tcgen05.fence::before_thread_sync;" ::: "memory");
            asm volatile("mbarrier.arrive.shared::cta.b64 _, [%0];"
                         :: "r"(sb + SM_EPI(p & 1)) : "memory");
        }
    }

    __syncthreads();
    if (wid == 0) {
        asm volatile("tcgen05.dealloc.cta_group::1.sync.aligned.b32 %0, %1;"
                     :: "r"(tmem), "r"(512u));
    }
#else
    // ---- generic-PTX fallback (compute_103 pass only; never runs on sm_103a) ----
    const int tid = threadIdx.x;
    const int m0 = blockIdx.x * BM;
    for (int r = 0; r < BM; ++r) {
        int m = m0 + r;
        int bi = m >> 14, ti = (m >> 6) & 255, ui = m & 63;
        const float* spp = src + (size_t)(bi * TT + ti) * DD;
        const float* tpp = tgt + (size_t)(bi * UU + ui) * DD;
        for (int c = tid; c < VV; c += THREADS) {
            const __half* wp = reinterpret_cast<const __half*>(g_wh) + (size_t)c * DD;
            float acc = bias[c];
            for (int k = 0; k < DD; ++k)
                acc += fmaxf(spp[k] + tpp[k], 0.0f) * __half2float(wp[k]);
            out[(size_t)m * VV + c] = acc;
        }
    }
#endif
}

// Prep: W -> fp16 (RN) into g_wh; lengths written as float VALUES into the tail.
__global__ void prep_kernel(const float* __restrict__ Wm,
                            const int* __restrict__ sl, const int* __restrict__ tl,
                            float* __restrict__ tail_dst, int extra) {
    int idx = blockIdx.x * 256 + threadIdx.x;     // 131072 float4 groups
    const float4 w4 = *reinterpret_cast<const float4*>(Wm + (size_t)idx * 4);
    uint2 o;
    o.x = pack_f16x2(w4.x, w4.y);
    o.y = pack_f16x2(w4.z, w4.w);
    *reinterpret_cast<uint2*>(g_wh + (size_t)idx * 2) = o;

    if (blockIdx.x == 0) {
        int i = threadIdx.x;
        if (i < 8 && extra >= 8)                        tail_dst[i] = (float)sl[i];
        else if (i >= 8 && i < 16 && extra >= 16)       tail_dst[i] = (float)tl[i - 8];
    }
}

// ---------------- host side ----------------

typedef CUresult (*PFN_encodeTiled_t)(
    CUtensorMap*, CUtensorMapDataType, cuuint32_t, void*,
    const cuuint64_t*, const cuuint64_t*, const cuuint32_t*, const cuuint32_t*,
    CUtensorMapInterleave, CUtensorMapSwizzle, CUtensorMapL2promotion,
    CUtensorMapFloatOOBfill);

extern "C" void kernel_launch(void* const* d_in, const int* in_sizes, int n_in,
                              void* d_out, int out_size) {
    const float* src  = (const float*)d_in[0];
    const int*   slen = (const int*)d_in[1];
    const float* tgt  = (const float*)d_in[2];
    const int*   tlen = (const int*)d_in[3];
    const float* Wm   = (const float*)d_in[4];
    const float* bias = (const float*)d_in[5];
    float* out = (float*)d_out;

    long long extra = (long long)out_size - (long long)M_TOTAL * VV;
    int extra_c = (int)(extra < 0 ? 0 : (extra > 16 ? 16 : extra));
    prep_kernel<<<VV * DD / 1024, 256>>>(Wm, slen, tlen,
                                         (float*)d_out + (long long)M_TOTAL * VV, extra_c);

    // Tensormap over g_wh: [1024 rows, 512 fp16], box [64, 128], SW128
    static CUtensorMap tmap;
    static bool tmap_ready = false;
    if (!tmap_ready) {
        void* whp = nullptr;
        cudaGetSymbolAddress(&whp, g_wh);
        void* fn = nullptr;
        cudaDriverEntryPointQueryResult qres;
        cudaGetDriverEntryPoint("cuTensorMapEncodeTiled", &fn,
                                cudaEnableDefault, &qres);
        PFN_encodeTiled_t encode = (PFN_encodeTiled_t)fn;
        cuuint64_t dims[2]    = { DD, VV };
        cuuint64_t strides[1] = { DD * 2 };
        cuuint32_t box[2]     = { BK, BN };          // 64 fp16 (=128B), 128 rows
        cuuint32_t estr[2]    = { 1, 1 };
        encode(&tmap, CU_TENSOR_MAP_DATA_TYPE_FLOAT16, 2, whp,
               dims, strides, box, estr,
               CU_TENSOR_MAP_INTERLEAVE_NONE, CU_TENSOR_MAP_SWIZZLE_128B,
               CU_TENSOR_MAP_L2_PROMOTION_L2_128B, CU_TENSOR_MAP_FLOAT_OOB_FILL_NONE);
        tmap_ready = true;
    }

    cudaFuncSetAttribute(joiner_f16_kernel,
                         cudaFuncAttributeMaxDynamicSharedMemorySize, SMEM_DYN);
    joiner_f16_kernel<<<M_TOTAL / BM, THREADS, SMEM_DYN>>>(src, tgt, bias, out, tmap);
}